// round 2
// baseline (speedup 1.0000x reference)
#include <cuda_runtime.h>
#include <cuda_bf16.h>
#include <math.h>

// ---------------------------------------------------------------------------
// Swin3D block: x[1,36864,512], c[1,512]
//   res = (4,96,96), window (2,6,12) -> N=144, nW=256, shift (1,3,6)
//   HEADS=16, hd=32, FFN hidden 2048
// All fp32. GEMMs use packed fp32x2 FMA (sm_100+).
// ---------------------------------------------------------------------------

#define L_TOK   36864
#define DMODEL  512
#define QKVDIM  1536
#define FFNDIM  2048
#define NWIN    256
#define WTOK    144      // tokens per window
#define NHEAD   16
#define HDIM    32

// ---------------- scratch (module-static device memory) --------------------
__device__ float g_xw  [L_TOK * DMODEL];   // shifted + window-partitioned x
__device__ float g_qkv [L_TOK * QKVDIM];
__device__ float g_aw  [L_TOK * DMODEL];   // attention out (window layout)
__device__ float g_pro [L_TOK * DMODEL];   // proj out (window layout)
__device__ float g_x1  [L_TOK * DMODEL];
__device__ float g_h   [L_TOK * FFNDIM];
__device__ float g_h2  [L_TOK * DMODEL];
__device__ float g_mod [2048];             // [shift1|scale1|shift2|scale2]

// ---------------- mod GEMV: silu(c) @ w_mod + b_mod -------------------------
__global__ void mod_kernel(const float* __restrict__ c,
                           const float* __restrict__ w1, const float* __restrict__ b1,
                           const float* __restrict__ w2, const float* __restrict__ b2,
                           float* __restrict__ gmod)
{
    __shared__ float sc[512];
    int tid = threadIdx.x;                       // 256 threads
    for (int i = tid; i < 512; i += 256) {
        float v = c[i];
        sc[i] = v / (1.0f + __expf(-v));
    }
    __syncthreads();
    int o = blockIdx.x * 256 + tid;              // 0..2047
    const float* w; const float* b; int col;
    if (o < 1024) { w = w1; b = b1; col = o; }
    else          { w = w2; b = b2; col = o - 1024; }
    float acc = b[col];
    for (int k = 0; k < 512; k++)
        acc += sc[k] * w[k * 1024 + col];
    gmod[o] = acc;
}

// ---------------- shift + window partition ----------------------------------
// xw[row, :] = x[src(row), :], row = win*144 + n
__global__ void partition_kernel(const float* __restrict__ x, float* __restrict__ xw)
{
    int row = blockIdx.x;
    int tid = threadIdx.x;                       // 128 threads -> one float4 each
    int win = row / WTOK, n = row % WTOK;
    int wb = win & 7, hb = (win >> 3) & 15, cb = win >> 7;
    int i = n / 72, rem = n % 72, j = rem / 12, k = rem % 12;
    int cs = cb * 2 + i, hs = hb * 6 + j, ws = wb * 12 + k;
    int c0 = (cs + 1) & 3;
    int h0 = hs + 3;  if (h0 >= 96) h0 -= 96;
    int w0 = ws + 6;  if (w0 >= 96) w0 -= 96;
    size_t src = (size_t)((c0 * 96 + h0) * 96 + w0) * DMODEL;
    const float4* s = (const float4*)(x + src);
    float4* d = (float4*)(xw + (size_t)row * DMODEL);
    d[tid] = s[tid];
}

// ---------------- tiled GEMM with fp32x2 packed FMA --------------------------
// C[M,N] = A[M,K] @ B[K,N] + bias, optional exact GELU.
// M%128==0, N%128==0, K%16==0 guaranteed by the problem shapes.
template<bool GELU>
__global__ __launch_bounds__(256)
void gemm_kernel(const float* __restrict__ A, const float* __restrict__ B,
                 const float* __restrict__ bias, float* __restrict__ C,
                 int M, int N, int K)
{
    __shared__ float As[16][128];
    __shared__ float Bs[16][128];

    int tid = threadIdx.x;
    int tx = tid & 15, ty = tid >> 4;
    int bm = blockIdx.y * 128, bn = blockIdx.x * 128;

    const float* Ab = A + (size_t)bm * K;
    const float* Bb = B + bn;

    unsigned long long acc[8][4];
    #pragma unroll
    for (int ii = 0; ii < 8; ii++)
        #pragma unroll
        for (int j2 = 0; j2 < 4; j2++) acc[ii][j2] = 0ull;

    for (int k0 = 0; k0 < K; k0 += 16) {
        #pragma unroll
        for (int l = 0; l < 2; l++) {
            int idx = l * 256 + tid;             // 0..511
            // A tile: 128 rows x 16 cols -> store transposed As[k][row]
            int r = idx >> 2, cv = idx & 3;
            float4 fa = *(const float4*)(Ab + (size_t)r * K + k0 + cv * 4);
            As[cv * 4 + 0][r] = fa.x;
            As[cv * 4 + 1][r] = fa.y;
            As[cv * 4 + 2][r] = fa.z;
            As[cv * 4 + 3][r] = fa.w;
            // B tile: 16 rows x 128 cols
            int br = idx >> 5, bc = idx & 31;
            *(float4*)(&Bs[br][bc * 4]) = *(const float4*)(Bb + (size_t)(k0 + br) * N + bc * 4);
        }
        __syncthreads();

        #pragma unroll
        for (int k = 0; k < 16; k++) {
            float a[8];
            *(float4*)(a)     = *(const float4*)&As[k][ty * 8];
            *(float4*)(a + 4) = *(const float4*)&As[k][ty * 8 + 4];
            const unsigned long long* bp = (const unsigned long long*)&Bs[k][tx * 8];
            unsigned long long b4[4];
            b4[0] = bp[0]; b4[1] = bp[1]; b4[2] = bp[2]; b4[3] = bp[3];
            #pragma unroll
            for (int ii = 0; ii < 8; ii++) {
                unsigned long long a2;
                asm("mov.b64 %0, {%1, %1};" : "=l"(a2) : "f"(a[ii]));
                #pragma unroll
                for (int j2 = 0; j2 < 4; j2++)
                    asm("fma.rn.f32x2 %0, %1, %2, %0;"
                        : "+l"(acc[ii][j2]) : "l"(a2), "l"(b4[j2]));
            }
        }
        __syncthreads();
    }

    // epilogue
    float bv[8];
    *(float4*)(bv)     = *(const float4*)(bias + bn + tx * 8);
    *(float4*)(bv + 4) = *(const float4*)(bias + bn + tx * 8 + 4);

    #pragma unroll
    for (int ii = 0; ii < 8; ii++) {
        float o[8];
        #pragma unroll
        for (int j2 = 0; j2 < 4; j2++)
            asm("mov.b64 {%0, %1}, %2;" : "=f"(o[2 * j2]), "=f"(o[2 * j2 + 1])
                : "l"(acc[ii][j2]));
        #pragma unroll
        for (int jj = 0; jj < 8; jj++) {
            float v = o[jj] + bv[jj];
            if (GELU) v = 0.5f * v * (1.0f + erff(v * 0.70710678118654752f));
            o[jj] = v;
        }
        float* crow = C + (size_t)(bm + ty * 8 + ii) * N + bn + tx * 8;
        *(float4*)(crow)     = *(float4*)(o);
        *(float4*)(crow + 4) = *(float4*)(o + 4);
    }
}

// ---------------- windowed attention ----------------------------------------
// grid = NWIN*NHEAD blocks, 128 threads. K,V staged in smem; Q via L1.
__global__ __launch_bounds__(128)
void attn_kernel(const float* __restrict__ qkv, float* __restrict__ aw)
{
    __shared__ float Ks[WTOK * HDIM];   // 18432 B
    __shared__ float Vs[WTOK * HDIM];   // 18432 B
    __shared__ float Pr[4 * WTOK];      //  2304 B
    __shared__ int   lbl[WTOK];         //   576 B

    int bid = blockIdx.x;
    int win = bid >> 4, head = bid & 15;
    int tid = threadIdx.x;
    int warp = tid >> 5, lane = tid & 31;

    int wb = win & 7, hb = (win >> 3) & 15, cb = win >> 7;

    const float* qbase = qkv + (size_t)win * WTOK * QKVDIM + head * HDIM;

    // stage K, V
    for (int idx = tid; idx < WTOK * HDIM; idx += 128) {
        int n = idx >> 5, d = idx & 31;
        Ks[idx] = qbase[(size_t)n * QKVDIM + 512 + d];
        Vs[idx] = qbase[(size_t)n * QKVDIM + 1024 + d];
    }
    // mask labels (shifted-window region id per position)
    // FIX(R1): strided loop — blockDim (128) < WTOK (144); previous guarded
    // write left lbl[128..143] uninitialized -> 12.5% rel_err.
    for (int n = tid; n < WTOK; n += 128) {
        int i = n / 72, rem = n % 72, j = rem / 12, k = rem % 12;
        int cs = cb * 2 + i, hs = hb * 6 + j, ws = wb * 12 + k;
        int lc = cs < 2 ? 0 : (cs < 3 ? 1 : 2);
        int lh = hs < 90 ? 0 : (hs < 93 ? 1 : 2);
        int lw = ws < 84 ? 0 : (ws < 90 ? 1 : 2);
        lbl[n] = lc * 9 + lh * 3 + lw;
    }
    __syncthreads();

    const float scale = 0.17677669529663688f;   // 1/sqrt(32)

    for (int i = warp; i < WTOK; i += 4) {
        int li = lbl[i];
        const float* qrow = qbase + (size_t)i * QKVDIM;

        float sc[5];
        #pragma unroll
        for (int cc = 0; cc < 5; cc++) sc[cc] = 0.0f;

        // rotated d-index -> conflict-free Ks reads, broadcastish Q reads
        for (int dd = 0; dd < 32; dd++) {
            int d = (dd + lane) & 31;
            float qd = __ldg(qrow + d);
            #pragma unroll
            for (int cc = 0; cc < 5; cc++) {
                int j = lane + 32 * cc;
                if (j < WTOK) sc[cc] += qd * Ks[j * HDIM + d];
            }
        }
        #pragma unroll
        for (int cc = 0; cc < 5; cc++) {
            int j = lane + 32 * cc;
            if (j < WTOK) sc[cc] = sc[cc] * scale + (lbl[j] == li ? 0.0f : -100.0f);
            else          sc[cc] = -1e30f;
        }
        // softmax
        float m = sc[0];
        #pragma unroll
        for (int cc = 1; cc < 5; cc++) m = fmaxf(m, sc[cc]);
        for (int o = 16; o; o >>= 1) m = fmaxf(m, __shfl_xor_sync(0xffffffffu, m, o));
        float p[5], sum = 0.0f;
        #pragma unroll
        for (int cc = 0; cc < 5; cc++) { p[cc] = __expf(sc[cc] - m); sum += p[cc]; }
        for (int o = 16; o; o >>= 1) sum += __shfl_xor_sync(0xffffffffu, sum, o);
        float inv = 1.0f / sum;
        #pragma unroll
        for (int cc = 0; cc < 5; cc++) {
            int j = lane + 32 * cc;
            if (j < WTOK) Pr[warp * WTOK + j] = p[cc] * inv;
        }
        __syncwarp();
        // out[i, lane] = sum_j p[j] * V[j, lane]
        float acc = 0.0f;
        for (int j = 0; j < WTOK; j++)
            acc += Pr[warp * WTOK + j] * Vs[j * HDIM + lane];
        aw[((size_t)win * WTOK + i) * DMODEL + head * HDIM + lane] = acc;
        __syncwarp();
    }
}

// ---------------- AdaLN + residual (optionally window-reverse gather) --------
// out[t] = base[t] + LN(src_row) * scale + shift
template<bool PERM>
__global__ __launch_bounds__(128)
void adaln_kernel(const float* __restrict__ base, const float* __restrict__ src,
                  const float* __restrict__ shift, const float* __restrict__ scl,
                  float* __restrict__ out)
{
    int t = blockIdx.x, tid = threadIdx.x;    // 128 threads x float4 = 512
    size_t srow;
    if (PERM) {
        int c0 = t / (96 * 96); int r = t % (96 * 96);
        int h0 = r / 96, w0 = r % 96;
        int cs = (c0 + 3) & 3;
        int hs = h0 - 3; if (hs < 0) hs += 96;
        int ws = w0 - 6; if (ws < 0) ws += 96;
        int cb = cs >> 1, i = cs & 1;
        int hb = hs / 6,  j = hs % 6;
        int wb = ws / 12, k = ws % 12;
        srow = (size_t)(((cb * 16 + hb) * 8 + wb) * WTOK + (i * 6 + j) * 12 + k);
    } else {
        srow = (size_t)t;
    }
    float4 v = ((const float4*)(src + srow * DMODEL))[tid];
    float s  = v.x + v.y + v.z + v.w;
    float sq = v.x * v.x + v.y * v.y + v.z * v.z + v.w * v.w;
    for (int o = 16; o; o >>= 1) {
        s  += __shfl_xor_sync(0xffffffffu, s,  o);
        sq += __shfl_xor_sync(0xffffffffu, sq, o);
    }
    __shared__ float rs[4], rq[4];
    int w = tid >> 5, ln = tid & 31;
    if (ln == 0) { rs[w] = s; rq[w] = sq; }
    __syncthreads();
    float S = rs[0] + rs[1] + rs[2] + rs[3];
    float Q = rq[0] + rq[1] + rq[2] + rq[3];
    float mean = S * (1.0f / 512.0f);
    float var  = Q * (1.0f / 512.0f) - mean * mean;
    float rstd = rsqrtf(var + 1e-5f);

    float4 sh = ((const float4*)shift)[tid];
    float4 sc = ((const float4*)scl)[tid];
    float4 bx = ((const float4*)(base + (size_t)t * DMODEL))[tid];
    float4 o;
    o.x = bx.x + (v.x - mean) * rstd * sc.x + sh.x;
    o.y = bx.y + (v.y - mean) * rstd * sc.y + sh.y;
    o.z = bx.z + (v.z - mean) * rstd * sc.z + sh.z;
    o.w = bx.w + (v.w - mean) * rstd * sc.w + sh.w;
    ((float4*)(out + (size_t)t * DMODEL))[tid] = o;
}

// ---------------------------------------------------------------------------
extern "C" void kernel_launch(void* const* d_in, const int* in_sizes, int n_in,
                              void* d_out, int out_size)
{
    (void)in_sizes; (void)n_in; (void)out_size;
    const float* x      = (const float*)d_in[0];
    const float* c      = (const float*)d_in[1];
    const float* w_qkv  = (const float*)d_in[2];
    const float* b_qkv  = (const float*)d_in[3];
    const float* w_proj = (const float*)d_in[4];
    const float* b_proj = (const float*)d_in[5];
    const float* w_fc1  = (const float*)d_in[6];
    const float* b_fc1  = (const float*)d_in[7];
    const float* w_fc2  = (const float*)d_in[8];
    const float* b_fc2  = (const float*)d_in[9];
    const float* w_mod1 = (const float*)d_in[10];
    const float* b_mod1 = (const float*)d_in[11];
    const float* w_mod2 = (const float*)d_in[12];
    const float* b_mod2 = (const float*)d_in[13];
    float* out = (float*)d_out;

    float *p_xw, *p_qkv, *p_aw, *p_pro, *p_x1, *p_h, *p_h2, *p_mod;
    cudaGetSymbolAddress((void**)&p_xw,  g_xw);
    cudaGetSymbolAddress((void**)&p_qkv, g_qkv);
    cudaGetSymbolAddress((void**)&p_aw,  g_aw);
    cudaGetSymbolAddress((void**)&p_pro, g_pro);
    cudaGetSymbolAddress((void**)&p_x1,  g_x1);
    cudaGetSymbolAddress((void**)&p_h,   g_h);
    cudaGetSymbolAddress((void**)&p_h2,  g_h2);
    cudaGetSymbolAddress((void**)&p_mod, g_mod);

    // 1. modulation vectors
    mod_kernel<<<8, 256>>>(c, w_mod1, b_mod1, w_mod2, b_mod2, p_mod);
    // 2. shift + window partition
    partition_kernel<<<L_TOK, 128>>>(x, p_xw);
    // 3. QKV GEMM
    gemm_kernel<false><<<dim3(QKVDIM / 128, L_TOK / 128), 256>>>(
        p_xw, w_qkv, b_qkv, p_qkv, L_TOK, QKVDIM, DMODEL);
    // 4. windowed attention
    attn_kernel<<<NWIN * NHEAD, 128>>>(p_qkv, p_aw);
    // 5. output projection
    gemm_kernel<false><<<dim3(DMODEL / 128, L_TOK / 128), 256>>>(
        p_aw, w_proj, b_proj, p_pro, L_TOK, DMODEL, DMODEL);
    // 6. window-reverse + unshift + AdaLN(mod1) + residual
    adaln_kernel<true><<<L_TOK, 128>>>(x, p_pro, p_mod, p_mod + 512, p_x1);
    // 7. FC1 + exact GELU
    gemm_kernel<true><<<dim3(FFNDIM / 128, L_TOK / 128), 256>>>(
        p_x1, w_fc1, b_fc1, p_h, L_TOK, FFNDIM, DMODEL);
    // 8. FC2
    gemm_kernel<false><<<dim3(DMODEL / 128, L_TOK / 128), 256>>>(
        p_h, w_fc2, b_fc2, p_h2, L_TOK, DMODEL, FFNDIM);
    // 9. AdaLN(mod2) + residual -> output
    adaln_kernel<false><<<L_TOK, 128>>>(p_x1, p_h2, p_mod + 1024, p_mod + 1536, out);
}

// round 3
// speedup vs baseline: 1.0107x; 1.0107x over previous
#include <cuda_runtime.h>
#include <cuda_bf16.h>
#include <math.h>

// ---------------------------------------------------------------------------
// Swin3D block: x[1,36864,512], c[1,512]
//   res = (4,96,96), window (2,6,12) -> N=144, nW=256, shift (1,3,6)
//   HEADS=16, hd=32, FFN hidden 2048
// All fp32. GEMMs use packed fp32x2 FMA (sm_100+), software-pipelined loads.
// ---------------------------------------------------------------------------

#define L_TOK   36864
#define DMODEL  512
#define QKVDIM  1536
#define FFNDIM  2048
#define NWIN    256
#define WTOK    144      // tokens per window
#define NHEAD   16
#define HDIM    32

// ---------------- scratch (module-static device memory) --------------------
__device__ float g_xw  [L_TOK * DMODEL];   // shifted + window-partitioned x
__device__ float g_qkv [L_TOK * QKVDIM];
__device__ float g_aw  [L_TOK * DMODEL];   // attention out (window layout)
__device__ float g_pro [L_TOK * DMODEL];   // proj out (window layout)
__device__ float g_x1  [L_TOK * DMODEL];
__device__ float g_h   [L_TOK * FFNDIM];
__device__ float g_h2  [L_TOK * DMODEL];
__device__ float g_mod [2048];             // [shift1|scale1|shift2|scale2]

// ---------------- mod GEMV: silu(c) @ w_mod + b_mod -------------------------
__global__ void mod_kernel(const float* __restrict__ c,
                           const float* __restrict__ w1, const float* __restrict__ b1,
                           const float* __restrict__ w2, const float* __restrict__ b2,
                           float* __restrict__ gmod)
{
    __shared__ float sc[512];
    int tid = threadIdx.x;                       // 256 threads
    for (int i = tid; i < 512; i += 256) {
        float v = c[i];
        sc[i] = v / (1.0f + __expf(-v));
    }
    __syncthreads();
    int o = blockIdx.x * 256 + tid;              // 0..2047
    const float* w; const float* b; int col;
    if (o < 1024) { w = w1; b = b1; col = o; }
    else          { w = w2; b = b2; col = o - 1024; }
    float acc = b[col];
    for (int k = 0; k < 512; k++)
        acc += sc[k] * w[k * 1024 + col];
    gmod[o] = acc;
}

// ---------------- shift + window partition ----------------------------------
__global__ void partition_kernel(const float* __restrict__ x, float* __restrict__ xw)
{
    int row = blockIdx.x;
    int tid = threadIdx.x;                       // 128 threads -> one float4 each
    int win = row / WTOK, n = row % WTOK;
    int wb = win & 7, hb = (win >> 3) & 15, cb = win >> 7;
    int i = n / 72, rem = n % 72, j = rem / 12, k = rem % 12;
    int cs = cb * 2 + i, hs = hb * 6 + j, ws = wb * 12 + k;
    int c0 = (cs + 1) & 3;
    int h0 = hs + 3;  if (h0 >= 96) h0 -= 96;
    int w0 = ws + 6;  if (w0 >= 96) w0 -= 96;
    size_t src = (size_t)((c0 * 96 + h0) * 96 + w0) * DMODEL;
    const float4* s = (const float4*)(x + src);
    float4* d = (float4*)(xw + (size_t)row * DMODEL);
    d[tid] = s[tid];
}

// ---------------- tiled GEMM, fp32x2 FMA, software-pipelined loads -----------
template<bool GELU>
__global__ __launch_bounds__(256)
void gemm_kernel(const float* __restrict__ A, const float* __restrict__ B,
                 const float* __restrict__ bias, float* __restrict__ C,
                 int M, int N, int K)
{
    __shared__ float As[16][128];
    __shared__ float Bs[16][128];

    int tid = threadIdx.x;
    int tx = tid & 15, ty = tid >> 4;
    int bm = blockIdx.y * 128, bn = blockIdx.x * 128;

    const float* Ab = A + (size_t)bm * K;
    const float* Bb = B + bn;

    int ar[2], ac[2], brr[2], bcc[2];
    #pragma unroll
    for (int l = 0; l < 2; l++) {
        int idx = l * 256 + tid;
        ar[l] = idx >> 2;  ac[l] = (idx & 3) * 4;
        brr[l] = idx >> 5; bcc[l] = (idx & 31) * 4;
    }

    float4 fa[2], fb[2];
    #pragma unroll
    for (int l = 0; l < 2; l++) {
        fa[l] = *(const float4*)(Ab + (size_t)ar[l] * K + ac[l]);
        fb[l] = *(const float4*)(Bb + (size_t)brr[l] * N + bcc[l]);
    }

    unsigned long long acc[8][4];
    #pragma unroll
    for (int ii = 0; ii < 8; ii++)
        #pragma unroll
        for (int j2 = 0; j2 < 4; j2++) acc[ii][j2] = 0ull;

    for (int k0 = 0; k0 < K; k0 += 16) {
        // store the tile fetched last round
        #pragma unroll
        for (int l = 0; l < 2; l++) {
            As[ac[l] + 0][ar[l]] = fa[l].x;
            As[ac[l] + 1][ar[l]] = fa[l].y;
            As[ac[l] + 2][ar[l]] = fa[l].z;
            As[ac[l] + 3][ar[l]] = fa[l].w;
            *(float4*)(&Bs[brr[l]][bcc[l]]) = fb[l];
        }
        __syncthreads();

        // prefetch next tile (overlaps with compute below)
        if (k0 + 16 < K) {
            #pragma unroll
            for (int l = 0; l < 2; l++) {
                fa[l] = *(const float4*)(Ab + (size_t)ar[l] * K + (k0 + 16) + ac[l]);
                fb[l] = *(const float4*)(Bb + (size_t)(k0 + 16 + brr[l]) * N + bcc[l]);
            }
        }

        #pragma unroll
        for (int k = 0; k < 16; k++) {
            float a[8];
            *(float4*)(a)     = *(const float4*)&As[k][ty * 8];
            *(float4*)(a + 4) = *(const float4*)&As[k][ty * 8 + 4];
            const unsigned long long* bp = (const unsigned long long*)&Bs[k][tx * 8];
            unsigned long long b4[4];
            b4[0] = bp[0]; b4[1] = bp[1]; b4[2] = bp[2]; b4[3] = bp[3];
            #pragma unroll
            for (int ii = 0; ii < 8; ii++) {
                unsigned long long a2;
                asm("mov.b64 %0, {%1, %1};" : "=l"(a2) : "f"(a[ii]));
                #pragma unroll
                for (int j2 = 0; j2 < 4; j2++)
                    asm("fma.rn.f32x2 %0, %1, %2, %0;"
                        : "+l"(acc[ii][j2]) : "l"(a2), "l"(b4[j2]));
            }
        }
        __syncthreads();
    }

    // epilogue
    float bv[8];
    *(float4*)(bv)     = *(const float4*)(bias + bn + tx * 8);
    *(float4*)(bv + 4) = *(const float4*)(bias + bn + tx * 8 + 4);

    #pragma unroll
    for (int ii = 0; ii < 8; ii++) {
        float o[8];
        #pragma unroll
        for (int j2 = 0; j2 < 4; j2++)
            asm("mov.b64 {%0, %1}, %2;" : "=f"(o[2 * j2]), "=f"(o[2 * j2 + 1])
                : "l"(acc[ii][j2]));
        #pragma unroll
        for (int jj = 0; jj < 8; jj++) {
            float v = o[jj] + bv[jj];
            if (GELU) v = 0.5f * v * (1.0f + erff(v * 0.70710678118654752f));
            o[jj] = v;
        }
        float* crow = C + (size_t)(bm + ty * 8 + ii) * N + bn + tx * 8;
        *(float4*)(crow)     = *(float4*)(o);
        *(float4*)(crow + 4) = *(float4*)(o + 4);
    }
}

// ---------------- windowed attention v2 --------------------------------------
// grid = NWIN*NHEAD blocks, 128 threads. 2 query rows per warp-iteration:
//  - Q in registers, rotated via SHFL (no per-iter LDG)
//  - each K-column LDS feeds 2 FMAs
//  - PV: half-warp per row, broadcast LDS.64 of V d-pairs
__global__ __launch_bounds__(128)
void attn_kernel(const float* __restrict__ qkv, float* __restrict__ aw)
{
    __shared__ __align__(16) float Ks[WTOK * HDIM];   // 18432 B
    __shared__ __align__(16) float Vs[WTOK * HDIM];   // 18432 B
    __shared__ float Pr[4][WTOK * 2];                 //  4608 B
    __shared__ int   lbl[WTOK];                       //   576 B

    int bid = blockIdx.x;
    int win = bid >> 4, head = bid & 15;
    int tid = threadIdx.x;
    int warp = tid >> 5, lane = tid & 31;

    int wb = win & 7, hb = (win >> 3) & 15, cb = win >> 7;

    const float* qbase = qkv + (size_t)win * WTOK * QKVDIM + head * HDIM;

    // stage K, V
    for (int idx = tid; idx < WTOK * HDIM; idx += 128) {
        int n = idx >> 5, d = idx & 31;
        Ks[idx] = qbase[(size_t)n * QKVDIM + 512 + d];
        Vs[idx] = qbase[(size_t)n * QKVDIM + 1024 + d];
    }
    // mask labels (strided: 144 > 128)
    for (int n = tid; n < WTOK; n += 128) {
        int i = n / 72, rem = n % 72, j = rem / 12, k = rem % 12;
        int cs = cb * 2 + i, hs = hb * 6 + j, ws = wb * 12 + k;
        int lc = cs < 2 ? 0 : (cs < 3 ? 1 : 2);
        int lh = hs < 90 ? 0 : (hs < 93 ? 1 : 2);
        int lw = ws < 84 ? 0 : (ws < 90 ? 1 : 2);
        lbl[n] = lc * 9 + lh * 3 + lw;
    }
    __syncthreads();

    const float scale = 0.17677669529663688f;   // 1/sqrt(32)

    // 72 row-pairs / 4 warps = 18 iterations of 2 rows
    for (int it = 0; it < 18; it++) {
        int i1 = it * 8 + warp * 2;
        int i2 = i1 + 1;
        int li1 = lbl[i1], li2 = lbl[i2];

        // Q rows in registers (one float per lane)
        float q1 = __ldg(qbase + (size_t)i1 * QKVDIM + lane);
        float q2 = __ldg(qbase + (size_t)i2 * QKVDIM + lane);

        float s1[5], s2[5];
        #pragma unroll
        for (int cc = 0; cc < 5; cc++) { s1[cc] = 0.0f; s2[cc] = 0.0f; }

        for (int dd = 0; dd < 32; dd++) {
            int d = (dd + lane) & 31;
            float qa = __shfl_sync(0xffffffffu, q1, d);
            float qb = __shfl_sync(0xffffffffu, q2, d);
            #pragma unroll
            for (int cc = 0; cc < 5; cc++) {
                int j = lane + 32 * cc;
                if (j < WTOK) {
                    float kv = Ks[j * HDIM + d];
                    s1[cc] += qa * kv;
                    s2[cc] += qb * kv;
                }
            }
        }
        // mask
        #pragma unroll
        for (int cc = 0; cc < 5; cc++) {
            int j = lane + 32 * cc;
            if (j < WTOK) {
                int lj = lbl[j];
                s1[cc] = s1[cc] * scale + (lj == li1 ? 0.0f : -100.0f);
                s2[cc] = s2[cc] * scale + (lj == li2 ? 0.0f : -100.0f);
            } else {
                s1[cc] = -1e30f; s2[cc] = -1e30f;
            }
        }
        // softmax (both rows)
        float m1 = s1[0], m2 = s2[0];
        #pragma unroll
        for (int cc = 1; cc < 5; cc++) { m1 = fmaxf(m1, s1[cc]); m2 = fmaxf(m2, s2[cc]); }
        for (int o = 16; o; o >>= 1) {
            m1 = fmaxf(m1, __shfl_xor_sync(0xffffffffu, m1, o));
            m2 = fmaxf(m2, __shfl_xor_sync(0xffffffffu, m2, o));
        }
        float p1[5], p2[5], sum1 = 0.0f, sum2 = 0.0f;
        #pragma unroll
        for (int cc = 0; cc < 5; cc++) {
            p1[cc] = __expf(s1[cc] - m1); sum1 += p1[cc];
            p2[cc] = __expf(s2[cc] - m2); sum2 += p2[cc];
        }
        for (int o = 16; o; o >>= 1) {
            sum1 += __shfl_xor_sync(0xffffffffu, sum1, o);
            sum2 += __shfl_xor_sync(0xffffffffu, sum2, o);
        }
        float inv1 = 1.0f / sum1, inv2 = 1.0f / sum2;
        #pragma unroll
        for (int cc = 0; cc < 5; cc++) {
            int j = lane + 32 * cc;
            if (j < WTOK) {
                Pr[warp][j * 2 + 0] = p1[cc] * inv1;
                Pr[warp][j * 2 + 1] = p2[cc] * inv2;
            }
        }
        __syncwarp();

        // PV: lanes 0-15 -> row i1, lanes 16-31 -> row i2; each lane owns d-pair.
        int half = lane >> 4;
        int dp = (lane & 15) * 2;
        float accx = 0.0f, accy = 0.0f;
        #pragma unroll 4
        for (int j = 0; j < WTOK; j++) {
            float2 v = *(const float2*)&Vs[j * HDIM + dp];   // broadcast across halves
            float p = Pr[warp][j * 2 + half];
            accx += p * v.x;
            accy += p * v.y;
        }
        int row = half ? i2 : i1;
        float* orow = aw + ((size_t)win * WTOK + row) * DMODEL + head * HDIM + dp;
        orow[0] = accx;
        orow[1] = accy;
        __syncwarp();
    }
}

// ---------------- AdaLN + residual (optionally window-reverse gather) --------
template<bool PERM>
__global__ __launch_bounds__(128)
void adaln_kernel(const float* __restrict__ base, const float* __restrict__ src,
                  const float* __restrict__ shift, const float* __restrict__ scl,
                  float* __restrict__ out)
{
    int t = blockIdx.x, tid = threadIdx.x;    // 128 threads x float4 = 512
    size_t srow;
    if (PERM) {
        int c0 = t / (96 * 96); int r = t % (96 * 96);
        int h0 = r / 96, w0 = r % 96;
        int cs = (c0 + 3) & 3;
        int hs = h0 - 3; if (hs < 0) hs += 96;
        int ws = w0 - 6; if (ws < 0) ws += 96;
        int cb = cs >> 1, i = cs & 1;
        int hb = hs / 6,  j = hs % 6;
        int wb = ws / 12, k = ws % 12;
        srow = (size_t)(((cb * 16 + hb) * 8 + wb) * WTOK + (i * 6 + j) * 12 + k);
    } else {
        srow = (size_t)t;
    }
    float4 v = ((const float4*)(src + srow * DMODEL))[tid];
    float s  = v.x + v.y + v.z + v.w;
    float sq = v.x * v.x + v.y * v.y + v.z * v.z + v.w * v.w;
    for (int o = 16; o; o >>= 1) {
        s  += __shfl_xor_sync(0xffffffffu, s,  o);
        sq += __shfl_xor_sync(0xffffffffu, sq, o);
    }
    __shared__ float rs[4], rq[4];
    int w = tid >> 5, ln = tid & 31;
    if (ln == 0) { rs[w] = s; rq[w] = sq; }
    __syncthreads();
    float S = rs[0] + rs[1] + rs[2] + rs[3];
    float Q = rq[0] + rq[1] + rq[2] + rq[3];
    float mean = S * (1.0f / 512.0f);
    float var  = Q * (1.0f / 512.0f) - mean * mean;
    float rstd = rsqrtf(var + 1e-5f);

    float4 sh = ((const float4*)shift)[tid];
    float4 sc = ((const float4*)scl)[tid];
    float4 bx = ((const float4*)(base + (size_t)t * DMODEL))[tid];
    float4 o;
    o.x = bx.x + (v.x - mean) * rstd * sc.x + sh.x;
    o.y = bx.y + (v.y - mean) * rstd * sc.y + sh.y;
    o.z = bx.z + (v.z - mean) * rstd * sc.z + sh.z;
    o.w = bx.w + (v.w - mean) * rstd * sc.w + sh.w;
    ((float4*)(out + (size_t)t * DMODEL))[tid] = o;
}

// ---------------------------------------------------------------------------
extern "C" void kernel_launch(void* const* d_in, const int* in_sizes, int n_in,
                              void* d_out, int out_size)
{
    (void)in_sizes; (void)n_in; (void)out_size;
    const float* x      = (const float*)d_in[0];
    const float* c      = (const float*)d_in[1];
    const float* w_qkv  = (const float*)d_in[2];
    const float* b_qkv  = (const float*)d_in[3];
    const float* w_proj = (const float*)d_in[4];
    const float* b_proj = (const float*)d_in[5];
    const float* w_fc1  = (const float*)d_in[6];
    const float* b_fc1  = (const float*)d_in[7];
    const float* w_fc2  = (const float*)d_in[8];
    const float* b_fc2  = (const float*)d_in[9];
    const float* w_mod1 = (const float*)d_in[10];
    const float* b_mod1 = (const float*)d_in[11];
    const float* w_mod2 = (const float*)d_in[12];
    const float* b_mod2 = (const float*)d_in[13];
    float* out = (float*)d_out;

    float *p_xw, *p_qkv, *p_aw, *p_pro, *p_x1, *p_h, *p_h2, *p_mod;
    cudaGetSymbolAddress((void**)&p_xw,  g_xw);
    cudaGetSymbolAddress((void**)&p_qkv, g_qkv);
    cudaGetSymbolAddress((void**)&p_aw,  g_aw);
    cudaGetSymbolAddress((void**)&p_pro, g_pro);
    cudaGetSymbolAddress((void**)&p_x1,  g_x1);
    cudaGetSymbolAddress((void**)&p_h,   g_h);
    cudaGetSymbolAddress((void**)&p_h2,  g_h2);
    cudaGetSymbolAddress((void**)&p_mod, g_mod);

    mod_kernel<<<8, 256>>>(c, w_mod1, b_mod1, w_mod2, b_mod2, p_mod);
    partition_kernel<<<L_TOK, 128>>>(x, p_xw);
    gemm_kernel<false><<<dim3(QKVDIM / 128, L_TOK / 128), 256>>>(
        p_xw, w_qkv, b_qkv, p_qkv, L_TOK, QKVDIM, DMODEL);
    attn_kernel<<<NWIN * NHEAD, 128>>>(p_qkv, p_aw);
    gemm_kernel<false><<<dim3(DMODEL / 128, L_TOK / 128), 256>>>(
        p_aw, w_proj, b_proj, p_pro, L_TOK, DMODEL, DMODEL);
    adaln_kernel<true><<<L_TOK, 128>>>(x, p_pro, p_mod, p_mod + 512, p_x1);
    gemm_kernel<true><<<dim3(FFNDIM / 128, L_TOK / 128), 256>>>(
        p_x1, w_fc1, b_fc1, p_h, L_TOK, FFNDIM, DMODEL);
    gemm_kernel<false><<<dim3(DMODEL / 128, L_TOK / 128), 256>>>(
        p_h, w_fc2, b_fc2, p_h2, L_TOK, DMODEL, FFNDIM);
    adaln_kernel<false><<<L_TOK, 128>>>(p_x1, p_h2, p_mod + 1024, p_mod + 1536, out);
}

// round 5
// speedup vs baseline: 2.0696x; 2.0478x over previous
#include <cuda_runtime.h>
#include <cuda_bf16.h>
#include <math.h>
#include <stdint.h>

// ---------------------------------------------------------------------------
// Swin3D block. GEMMs on mma.sync m16n8k16 bf16 split-precision (hi+lo,
// 3 MMAs, fp32 accum) with cp.async double-buffered smem. (tcgen05 is not
// available: harness compiles PTX at compute_100, no 'a' feature target.)
// ---------------------------------------------------------------------------

#define L_TOK   36864
#define DMODEL  512
#define QKVDIM  1536
#define FFNDIM  2048
#define NWIN    256
#define WTOK    144
#define NHEAD   16
#define HDIM    32

typedef __nv_bfloat16 bf16;

// ---------------- scratch ---------------------------------------------------
__device__ bf16  g_xw_h [L_TOK * DMODEL], g_xw_l [L_TOK * DMODEL];
__device__ float g_qkv  [L_TOK * QKVDIM];
__device__ bf16  g_aw_h [L_TOK * DMODEL], g_aw_l [L_TOK * DMODEL];
__device__ float g_pro  [L_TOK * DMODEL];
__device__ float g_x1   [L_TOK * DMODEL];
__device__ bf16  g_x1_h [L_TOK * DMODEL], g_x1_l [L_TOK * DMODEL];
__device__ bf16  g_h_h  [L_TOK * FFNDIM], g_h_l  [L_TOK * FFNDIM];
__device__ float g_h2   [L_TOK * DMODEL];
__device__ float g_mod  [2048];

// pre-transposed + bf16-split weights, layout [N][K]
__device__ bf16 g_wqkv_h[QKVDIM * DMODEL], g_wqkv_l[QKVDIM * DMODEL];
__device__ bf16 g_wproj_h[DMODEL * DMODEL], g_wproj_l[DMODEL * DMODEL];
__device__ bf16 g_wfc1_h [FFNDIM * DMODEL], g_wfc1_l [FFNDIM * DMODEL];
__device__ bf16 g_wfc2_h [DMODEL * FFNDIM], g_wfc2_l [DMODEL * FFNDIM];

// ---------------- helpers ---------------------------------------------------
__device__ __forceinline__ uint32_t smem_u32(const void* p) {
    uint32_t a;
    asm("{ .reg .u64 t; cvta.to.shared.u64 t, %1; cvt.u32.u64 %0, t; }" : "=r"(a) : "l"(p));
    return a;
}
// pack: a -> low 16 bits (element col), b -> high 16 bits (element col+1)
__device__ __forceinline__ uint32_t packlh(float a, float b) {
    uint32_t r;
    asm("cvt.rn.bf16x2.f32 %0, %1, %2;" : "=r"(r) : "f"(b), "f"(a));
    return r;
}
__device__ __forceinline__ void cpa16(uint32_t dst, const void* src) {
    asm volatile("cp.async.cg.shared.global [%0], [%1], 16;" :: "r"(dst), "l"(src) : "memory");
}
__device__ __forceinline__ void cp_commit() {
    asm volatile("cp.async.commit_group;" ::: "memory");
}
template<int N>
__device__ __forceinline__ void cp_wait() {
    asm volatile("cp.async.wait_group %0;" :: "n"(N) : "memory");
}
__device__ __forceinline__ void ldm4(uint32_t* r, uint32_t addr) {
    asm volatile("ldmatrix.sync.aligned.m8n8.x4.shared.b16 {%0,%1,%2,%3}, [%4];"
                 : "=r"(r[0]), "=r"(r[1]), "=r"(r[2]), "=r"(r[3]) : "r"(addr));
}
__device__ __forceinline__ void mma16816(float* d, const uint32_t* a,
                                         uint32_t b0, uint32_t b1) {
    asm volatile(
        "mma.sync.aligned.m16n8k16.row.col.f32.bf16.bf16.f32 "
        "{%0,%1,%2,%3},{%4,%5,%6,%7},{%8,%9},{%0,%1,%2,%3};"
        : "+f"(d[0]), "+f"(d[1]), "+f"(d[2]), "+f"(d[3])
        : "r"(a[0]), "r"(a[1]), "r"(a[2]), "r"(a[3]), "r"(b0), "r"(b1));
}

// ---------------- weight transpose + bf16 split -----------------------------
__global__ void wconv_kernel(const float* __restrict__ w,
                             bf16* __restrict__ oh, bf16* __restrict__ ol,
                             int K, int N)
{
    __shared__ float t[32][33];
    int n0 = blockIdx.x * 32, k0 = blockIdx.y * 32;
    int tx = threadIdx.x, ty = threadIdx.y;   // (32, 8)
    for (int i = ty; i < 32; i += 8)
        t[i][tx] = w[(size_t)(k0 + i) * N + n0 + tx];
    __syncthreads();
    for (int i = ty; i < 32; i += 8) {
        float f = t[tx][i];                    // = w[k0+tx][n0+i]
        bf16 h = __float2bfloat16(f);
        bf16 l = __float2bfloat16(f - __bfloat162float(h));
        size_t o = (size_t)(n0 + i) * K + k0 + tx;
        oh[o] = h; ol[o] = l;
    }
}

// ---------------- mma.sync split-bf16 GEMM -----------------------------------
// C[M,N] = (Ah+Al)[M,K] @ (Bh+Bl)^T   (B stored [N][K]), + bias, opt GELU.
// Output: fp32 (Cf) or bf16 hi/lo split (Ch, Cl).
#define GST 32768u       // bytes per stage
#define GOA_H 0u
#define GOA_L 8192u
#define GOB_H 16384u
#define GOB_L 24576u

template<bool GELU, bool OUTSPLIT>
__global__ __launch_bounds__(256)
void gemm_mma(const bf16* __restrict__ Ah, const bf16* __restrict__ Al,
              const bf16* __restrict__ Bh, const bf16* __restrict__ Bl,
              const float* __restrict__ bias,
              float* __restrict__ Cf, bf16* __restrict__ Ch, bf16* __restrict__ Cl,
              int M, int N, int K)
{
    extern __shared__ char smc[];
    uint32_t sb = smem_u32(smc);
    int tid = threadIdx.x, wid = tid >> 5, lane = tid & 31;
    int wm = wid & 1, wn = wid >> 1;            // warp tile: 64x32
    int bm = blockIdx.y * 128, bn = blockIdx.x * 128;

    // ---- cp.async mapping: each thread: 1 row, chunks c0, c0+1 (16B each)
    int id0 = tid * 2;
    int row = id0 >> 2, c0 = id0 & 3;           // c0 in {0, 2}
    uint32_t doff[2]; int soff[2];
    #pragma unroll
    for (int l = 0; l < 2; l++) {
        int c = c0 + l;
        doff[l] = (uint32_t)(row * 64 + ((c ^ (row & 3)) << 4));
        soff[l] = c * 8;
    }
    const bf16* pAh = Ah + (size_t)(bm + row) * K;
    const bf16* pAl = Al + (size_t)(bm + row) * K;
    const bf16* pBh = Bh + (size_t)(bn + row) * K;
    const bf16* pBl = Bl + (size_t)(bn + row) * K;

    float acc[4][4][4];
    #pragma unroll
    for (int i = 0; i < 4; i++)
        #pragma unroll
        for (int j = 0; j < 4; j++)
            #pragma unroll
            for (int q = 0; q < 4; q++) acc[i][j][q] = 0.0f;

    int NC = K >> 5;

    // prologue: stage 0
    {
        uint32_t base = sb;
        #pragma unroll
        for (int l = 0; l < 2; l++) {
            cpa16(base + GOA_H + doff[l], pAh + soff[l]);
            cpa16(base + GOA_L + doff[l], pAl + soff[l]);
            cpa16(base + GOB_H + doff[l], pBh + soff[l]);
            cpa16(base + GOB_L + doff[l], pBl + soff[l]);
        }
        cp_commit();
    }

    // precomputed ldmatrix coords
    int arow = wm * 64 + (lane & 15);
    int akh  = lane >> 4;                     // chunk half for A
    int brow = wn * 32 + (lane & 7) + ((lane >> 4) & 1) * 8;
    int bkh  = (lane >> 3) & 1;

    for (int kc = 0; kc < NC; kc++) {
        if (kc + 1 < NC) {
            uint32_t base = sb + ((kc + 1) & 1) * GST;
            int kof = (kc + 1) * 32;
            #pragma unroll
            for (int l = 0; l < 2; l++) {
                cpa16(base + GOA_H + doff[l], pAh + kof + soff[l]);
                cpa16(base + GOA_L + doff[l], pAl + kof + soff[l]);
                cpa16(base + GOB_H + doff[l], pBh + kof + soff[l]);
                cpa16(base + GOB_L + doff[l], pBl + kof + soff[l]);
            }
            cp_commit();
            cp_wait<1>();
        } else {
            cp_wait<0>();
        }
        __syncthreads();

        uint32_t base = sb + (kc & 1) * GST;
        #pragma unroll
        for (int ks = 0; ks < 2; ks++) {
            uint32_t ah[4][4], al[4][4], bh[2][4], bl[2][4];
            #pragma unroll
            for (int ma = 0; ma < 4; ma++) {
                int r = arow + ma * 16;
                int c = ks * 2 + akh;
                uint32_t off = (uint32_t)(r * 64 + ((c ^ (r & 3)) << 4));
                ldm4(ah[ma], base + GOA_H + off);
                ldm4(al[ma], base + GOA_L + off);
            }
            #pragma unroll
            for (int p = 0; p < 2; p++) {
                int r = brow + p * 16;
                int c = ks * 2 + bkh;
                uint32_t off = (uint32_t)(r * 64 + ((c ^ (r & 3)) << 4));
                ldm4(bh[p], base + GOB_H + off);
                ldm4(bl[p], base + GOB_L + off);
            }
            #pragma unroll
            for (int ma = 0; ma < 4; ma++)
                #pragma unroll
                for (int na = 0; na < 4; na++) {
                    uint32_t bh0 = bh[na >> 1][(na & 1) * 2];
                    uint32_t bh1 = bh[na >> 1][(na & 1) * 2 + 1];
                    uint32_t bl0 = bl[na >> 1][(na & 1) * 2];
                    uint32_t bl1 = bl[na >> 1][(na & 1) * 2 + 1];
                    mma16816(acc[ma][na], ah[ma], bh0, bh1);
                    mma16816(acc[ma][na], ah[ma], bl0, bl1);
                    mma16816(acc[ma][na], al[ma], bh0, bh1);
                }
        }
        __syncthreads();
    }

    // ---- epilogue
    int l4 = lane >> 2, l2 = (lane & 3) * 2;
    #pragma unroll
    for (int ma = 0; ma < 4; ma++) {
        int grow = bm + wm * 64 + ma * 16 + l4;
        #pragma unroll
        for (int na = 0; na < 4; na++) {
            int gcol = bn + wn * 32 + na * 8 + l2;
            float b0 = __ldg(bias + gcol), b1 = __ldg(bias + gcol + 1);
            float v[4];
            v[0] = acc[ma][na][0] + b0;  v[1] = acc[ma][na][1] + b1;
            v[2] = acc[ma][na][2] + b0;  v[3] = acc[ma][na][3] + b1;
            if (GELU) {
                #pragma unroll
                for (int q = 0; q < 4; q++)
                    v[q] = 0.5f * v[q] * (1.0f + erff(v[q] * 0.70710678118654752f));
            }
            #pragma unroll
            for (int half = 0; half < 2; half++) {
                size_t o = (size_t)(grow + half * 8) * N + gcol;
                float va = v[half * 2], vb = v[half * 2 + 1];
                if (OUTSPLIT) {
                    uint32_t hi = packlh(va, vb);
                    float la = va - __uint_as_float(hi << 16);
                    float lb = vb - __uint_as_float(hi & 0xffff0000u);
                    *(uint32_t*)(Ch + o) = hi;
                    *(uint32_t*)(Cl + o) = packlh(la, lb);
                } else {
                    float2 st; st.x = va; st.y = vb;
                    *(float2*)(Cf + o) = st;
                }
            }
        }
    }
}

// ---------------- mod GEMV ---------------------------------------------------
__global__ void mod_kernel(const float* __restrict__ c,
                           const float* __restrict__ w1, const float* __restrict__ b1,
                           const float* __restrict__ w2, const float* __restrict__ b2,
                           float* __restrict__ gmod)
{
    __shared__ float sc[512];
    int tid = threadIdx.x;
    for (int i = tid; i < 512; i += 256) {
        float v = c[i];
        sc[i] = v / (1.0f + __expf(-v));
    }
    __syncthreads();
    int o = blockIdx.x * 256 + tid;
    const float* w; const float* b; int col;
    if (o < 1024) { w = w1; b = b1; col = o; }
    else          { w = w2; b = b2; col = o - 1024; }
    float acc = b[col];
    for (int k = 0; k < 512; k++)
        acc += sc[k] * w[k * 1024 + col];
    gmod[o] = acc;
}

// ---------------- shift + window partition -> bf16 hi/lo ---------------------
__global__ void partition_kernel(const float* __restrict__ x,
                                 bf16* __restrict__ xh, bf16* __restrict__ xl)
{
    int row = blockIdx.x;
    int tid = threadIdx.x;                     // 128 threads, float4 each
    int win = row / WTOK, n = row % WTOK;
    int wb = win & 7, hb = (win >> 3) & 15, cb = win >> 7;
    int i = n / 72, rem = n % 72, j = rem / 12, k = rem % 12;
    int cs = cb * 2 + i, hs = hb * 6 + j, ws = wb * 12 + k;
    int c0 = (cs + 1) & 3;
    int h0 = hs + 3;  if (h0 >= 96) h0 -= 96;
    int w0 = ws + 6;  if (w0 >= 96) w0 -= 96;
    size_t src = (size_t)((c0 * 96 + h0) * 96 + w0) * DMODEL;
    float4 f = ((const float4*)(x + src))[tid];
    uint32_t h01 = packlh(f.x, f.y), h23 = packlh(f.z, f.w);
    float l0 = f.x - __uint_as_float(h01 << 16);
    float l1 = f.y - __uint_as_float(h01 & 0xffff0000u);
    float l2 = f.z - __uint_as_float(h23 << 16);
    float l3 = f.w - __uint_as_float(h23 & 0xffff0000u);
    size_t o = (size_t)row * DMODEL + tid * 4;
    *(uint2*)(xh + o) = make_uint2(h01, h23);
    *(uint2*)(xl + o) = make_uint2(packlh(l0, l1), packlh(l2, l3));
}

// ---------------- windowed attention (fp32 math, bf16-split output) ----------
__global__ __launch_bounds__(128)
void attn_kernel(const float* __restrict__ qkv,
                 bf16* __restrict__ awh, bf16* __restrict__ awl)
{
    __shared__ __align__(16) float Ks[WTOK * HDIM];
    __shared__ __align__(16) float Vs[WTOK * HDIM];
    __shared__ float Pr[4][WTOK * 2];
    __shared__ int   lbl[WTOK];

    int bid = blockIdx.x;
    int win = bid >> 4, head = bid & 15;
    int tid = threadIdx.x;
    int warp = tid >> 5, lane = tid & 31;
    int wb = win & 7, hb = (win >> 3) & 15, cb = win >> 7;

    const float* qbase = qkv + (size_t)win * WTOK * QKVDIM + head * HDIM;

    for (int idx = tid; idx < WTOK * HDIM; idx += 128) {
        int n = idx >> 5, d = idx & 31;
        Ks[idx] = qbase[(size_t)n * QKVDIM + 512 + d];
        Vs[idx] = qbase[(size_t)n * QKVDIM + 1024 + d];
    }
    for (int n = tid; n < WTOK; n += 128) {
        int i = n / 72, rem = n % 72, j = rem / 12, k = rem % 12;
        int cs = cb * 2 + i, hs = hb * 6 + j, ws = wb * 12 + k;
        int lc = cs < 2 ? 0 : (cs < 3 ? 1 : 2);
        int lh = hs < 90 ? 0 : (hs < 93 ? 1 : 2);
        int lw = ws < 84 ? 0 : (ws < 90 ? 1 : 2);
        lbl[n] = lc * 9 + lh * 3 + lw;
    }
    __syncthreads();

    const float scale = 0.17677669529663688f;

    for (int it = 0; it < 18; it++) {
        int i1 = it * 8 + warp * 2;
        int i2 = i1 + 1;
        int li1 = lbl[i1], li2 = lbl[i2];
        float q1 = __ldg(qbase + (size_t)i1 * QKVDIM + lane);
        float q2 = __ldg(qbase + (size_t)i2 * QKVDIM + lane);

        float s1[5], s2[5];
        #pragma unroll
        for (int cc = 0; cc < 5; cc++) { s1[cc] = 0.0f; s2[cc] = 0.0f; }
        for (int dd = 0; dd < 32; dd++) {
            int d = (dd + lane) & 31;
            float qa = __shfl_sync(0xffffffffu, q1, d);
            float qb = __shfl_sync(0xffffffffu, q2, d);
            #pragma unroll
            for (int cc = 0; cc < 5; cc++) {
                int j = lane + 32 * cc;
                if (j < WTOK) {
                    float kv = Ks[j * HDIM + d];
                    s1[cc] += qa * kv;
                    s2[cc] += qb * kv;
                }
            }
        }
        #pragma unroll
        for (int cc = 0; cc < 5; cc++) {
            int j = lane + 32 * cc;
            if (j < WTOK) {
                int lj = lbl[j];
                s1[cc] = s1[cc] * scale + (lj == li1 ? 0.0f : -100.0f);
                s2[cc] = s2[cc] * scale + (lj == li2 ? 0.0f : -100.0f);
            } else { s1[cc] = -1e30f; s2[cc] = -1e30f; }
        }
        float m1 = s1[0], m2 = s2[0];
        #pragma unroll
        for (int cc = 1; cc < 5; cc++) { m1 = fmaxf(m1, s1[cc]); m2 = fmaxf(m2, s2[cc]); }
        for (int o = 16; o; o >>= 1) {
            m1 = fmaxf(m1, __shfl_xor_sync(0xffffffffu, m1, o));
            m2 = fmaxf(m2, __shfl_xor_sync(0xffffffffu, m2, o));
        }
        float p1[5], p2[5], sum1 = 0.0f, sum2 = 0.0f;
        #pragma unroll
        for (int cc = 0; cc < 5; cc++) {
            p1[cc] = __expf(s1[cc] - m1); sum1 += p1[cc];
            p2[cc] = __expf(s2[cc] - m2); sum2 += p2[cc];
        }
        for (int o = 16; o; o >>= 1) {
            sum1 += __shfl_xor_sync(0xffffffffu, sum1, o);
            sum2 += __shfl_xor_sync(0xffffffffu, sum2, o);
        }
        float inv1 = 1.0f / sum1, inv2 = 1.0f / sum2;
        #pragma unroll
        for (int cc = 0; cc < 5; cc++) {
            int j = lane + 32 * cc;
            if (j < WTOK) {
                Pr[warp][j * 2 + 0] = p1[cc] * inv1;
                Pr[warp][j * 2 + 1] = p2[cc] * inv2;
            }
        }
        __syncwarp();
        int half = lane >> 4;
        int dp = (lane & 15) * 2;
        float accx = 0.0f, accy = 0.0f;
        #pragma unroll 4
        for (int j = 0; j < WTOK; j++) {
            float2 v = *(const float2*)&Vs[j * HDIM + dp];
            float p = Pr[warp][j * 2 + half];
            accx += p * v.x;
            accy += p * v.y;
        }
        int row = half ? i2 : i1;
        size_t o = ((size_t)win * WTOK + row) * DMODEL + head * HDIM + dp;
        uint32_t hi = packlh(accx, accy);
        float lx = accx - __uint_as_float(hi << 16);
        float ly = accy - __uint_as_float(hi & 0xffff0000u);
        *(uint32_t*)(awh + o) = hi;
        *(uint32_t*)(awl + o) = packlh(lx, ly);
        __syncwarp();
    }
}

// ---------------- AdaLN + residual -------------------------------------------
template<bool PERM, bool SPLITOUT>
__global__ __launch_bounds__(128)
void adaln_kernel(const float* __restrict__ base, const float* __restrict__ src,
                  const float* __restrict__ shift, const float* __restrict__ scl,
                  float* __restrict__ out, bf16* __restrict__ oh, bf16* __restrict__ ol)
{
    int t = blockIdx.x, tid = threadIdx.x;
    size_t srow;
    if (PERM) {
        int c0 = t / (96 * 96); int r = t % (96 * 96);
        int h0 = r / 96, w0 = r % 96;
        int cs = (c0 + 3) & 3;
        int hs = h0 - 3; if (hs < 0) hs += 96;
        int ws = w0 - 6; if (ws < 0) ws += 96;
        int cb = cs >> 1, i = cs & 1;
        int hb = hs / 6,  j = hs % 6;
        int wb = ws / 12, k = ws % 12;
        srow = (size_t)(((cb * 16 + hb) * 8 + wb) * WTOK + (i * 6 + j) * 12 + k);
    } else {
        srow = (size_t)t;
    }
    float4 v = ((const float4*)(src + srow * DMODEL))[tid];
    float s  = v.x + v.y + v.z + v.w;
    float sq = v.x * v.x + v.y * v.y + v.z * v.z + v.w * v.w;
    for (int o = 16; o; o >>= 1) {
        s  += __shfl_xor_sync(0xffffffffu, s,  o);
        sq += __shfl_xor_sync(0xffffffffu, sq, o);
    }
    __shared__ float rs[4], rq[4];
    int w = tid >> 5, ln = tid & 31;
    if (ln == 0) { rs[w] = s; rq[w] = sq; }
    __syncthreads();
    float S = rs[0] + rs[1] + rs[2] + rs[3];
    float Q = rq[0] + rq[1] + rq[2] + rq[3];
    float mean = S * (1.0f / 512.0f);
    float var  = Q * (1.0f / 512.0f) - mean * mean;
    float rstd = rsqrtf(var + 1e-5f);

    float4 sh = ((const float4*)shift)[tid];
    float4 sc = ((const float4*)scl)[tid];
    float4 bx = ((const float4*)(base + (size_t)t * DMODEL))[tid];
    float4 o;
    o.x = bx.x + (v.x - mean) * rstd * sc.x + sh.x;
    o.y = bx.y + (v.y - mean) * rstd * sc.y + sh.y;
    o.z = bx.z + (v.z - mean) * rstd * sc.z + sh.z;
    o.w = bx.w + (v.w - mean) * rstd * sc.w + sh.w;
    ((float4*)(out + (size_t)t * DMODEL))[tid] = o;
    if (SPLITOUT) {
        uint32_t h01 = packlh(o.x, o.y), h23 = packlh(o.z, o.w);
        float l0 = o.x - __uint_as_float(h01 << 16);
        float l1 = o.y - __uint_as_float(h01 & 0xffff0000u);
        float l2 = o.z - __uint_as_float(h23 << 16);
        float l3 = o.w - __uint_as_float(h23 & 0xffff0000u);
        size_t oo = (size_t)t * DMODEL + tid * 4;
        *(uint2*)(oh + oo) = make_uint2(h01, h23);
        *(uint2*)(ol + oo) = make_uint2(packlh(l0, l1), packlh(l2, l3));
    }
}

// ---------------------------------------------------------------------------
extern "C" void kernel_launch(void* const* d_in, const int* in_sizes, int n_in,
                              void* d_out, int out_size)
{
    (void)in_sizes; (void)n_in; (void)out_size;
    const float* x      = (const float*)d_in[0];
    const float* c      = (const float*)d_in[1];
    const float* w_qkv  = (const float*)d_in[2];
    const float* b_qkv  = (const float*)d_in[3];
    const float* w_proj = (const float*)d_in[4];
    const float* b_proj = (const float*)d_in[5];
    const float* w_fc1  = (const float*)d_in[6];
    const float* b_fc1  = (const float*)d_in[7];
    const float* w_fc2  = (const float*)d_in[8];
    const float* b_fc2  = (const float*)d_in[9];
    const float* w_mod1 = (const float*)d_in[10];
    const float* b_mod1 = (const float*)d_in[11];
    const float* w_mod2 = (const float*)d_in[12];
    const float* b_mod2 = (const float*)d_in[13];
    float* out = (float*)d_out;

    float *p_qkv, *p_pro, *p_x1, *p_h2, *p_mod;
    bf16 *p_xwh, *p_xwl, *p_awh, *p_awl, *p_x1h, *p_x1l, *p_hh, *p_hl;
    cudaGetSymbolAddress((void**)&p_qkv, g_qkv);
    cudaGetSymbolAddress((void**)&p_pro, g_pro);
    cudaGetSymbolAddress((void**)&p_x1,  g_x1);
    cudaGetSymbolAddress((void**)&p_h2,  g_h2);
    cudaGetSymbolAddress((void**)&p_mod, g_mod);
    cudaGetSymbolAddress((void**)&p_xwh, g_xw_h); cudaGetSymbolAddress((void**)&p_xwl, g_xw_l);
    cudaGetSymbolAddress((void**)&p_awh, g_aw_h); cudaGetSymbolAddress((void**)&p_awl, g_aw_l);
    cudaGetSymbolAddress((void**)&p_x1h, g_x1_h); cudaGetSymbolAddress((void**)&p_x1l, g_x1_l);
    cudaGetSymbolAddress((void**)&p_hh,  g_h_h);  cudaGetSymbolAddress((void**)&p_hl,  g_h_l);

    bf16 *qh, *ql, *ph, *pl, *f1h, *f1l, *f2h, *f2l;
    cudaGetSymbolAddress((void**)&qh,  g_wqkv_h);  cudaGetSymbolAddress((void**)&ql,  g_wqkv_l);
    cudaGetSymbolAddress((void**)&ph,  g_wproj_h); cudaGetSymbolAddress((void**)&pl,  g_wproj_l);
    cudaGetSymbolAddress((void**)&f1h, g_wfc1_h);  cudaGetSymbolAddress((void**)&f1l, g_wfc1_l);
    cudaGetSymbolAddress((void**)&f2h, g_wfc2_h);  cudaGetSymbolAddress((void**)&f2l, g_wfc2_l);

    const int SMEM = 65536;
    cudaFuncSetAttribute(gemm_mma<false,false>, cudaFuncAttributeMaxDynamicSharedMemorySize, SMEM);
    cudaFuncSetAttribute(gemm_mma<true,true>,   cudaFuncAttributeMaxDynamicSharedMemorySize, SMEM);

    dim3 wcb(32, 8);
    wconv_kernel<<<dim3(QKVDIM / 32, DMODEL / 32), wcb>>>(w_qkv,  qh,  ql,  DMODEL, QKVDIM);
    wconv_kernel<<<dim3(DMODEL / 32, DMODEL / 32), wcb>>>(w_proj, ph,  pl,  DMODEL, DMODEL);
    wconv_kernel<<<dim3(FFNDIM / 32, DMODEL / 32), wcb>>>(w_fc1,  f1h, f1l, DMODEL, FFNDIM);
    wconv_kernel<<<dim3(DMODEL / 32, FFNDIM / 32), wcb>>>(w_fc2,  f2h, f2l, FFNDIM, DMODEL);

    mod_kernel<<<8, 256>>>(c, w_mod1, b_mod1, w_mod2, b_mod2, p_mod);
    partition_kernel<<<L_TOK, 128>>>(x, p_xwh, p_xwl);

    gemm_mma<false,false><<<dim3(QKVDIM / 128, L_TOK / 128), 256, SMEM>>>(
        p_xwh, p_xwl, qh, ql, b_qkv, p_qkv, nullptr, nullptr, L_TOK, QKVDIM, DMODEL);
    attn_kernel<<<NWIN * NHEAD, 128>>>(p_qkv, p_awh, p_awl);
    gemm_mma<false,false><<<dim3(DMODEL / 128, L_TOK / 128), 256, SMEM>>>(
        p_awh, p_awl, ph, pl, b_proj, p_pro, nullptr, nullptr, L_TOK, DMODEL, DMODEL);
    adaln_kernel<true,true><<<L_TOK, 128>>>(x, p_pro, p_mod, p_mod + 512, p_x1, p_x1h, p_x1l);
    gemm_mma<true,true><<<dim3(FFNDIM / 128, L_TOK / 128), 256, SMEM>>>(
        p_x1h, p_x1l, f1h, f1l, b_fc1, nullptr, p_hh, p_hl, L_TOK, FFNDIM, DMODEL);
    gemm_mma<false,false><<<dim3(DMODEL / 128, L_TOK / 128), 256, SMEM>>>(
        p_hh, p_hl, f2h, f2l, b_fc2, p_h2, nullptr, nullptr, L_TOK, DMODEL, FFNDIM);
    adaln_kernel<false,false><<<L_TOK, 128>>>(p_x1, p_h2, p_mod + 1024, p_mod + 1536,
                                              out, nullptr, nullptr);
}

// round 6
// speedup vs baseline: 2.2879x; 1.1055x over previous
#include <cuda_runtime.h>
#include <cuda_bf16.h>
#include <math.h>
#include <stdint.h>

// ---------------------------------------------------------------------------
// Swin3D block. GEMMs + attention on mma.sync m16n8k16 bf16 split-precision
// (hi+lo, 3 MMAs, fp32 accum). tcgen05 unavailable (harness targets compute_100).
// ---------------------------------------------------------------------------

#define L_TOK   36864
#define DMODEL  512
#define QKVDIM  1536
#define FFNDIM  2048
#define NWIN    256
#define WTOK    144
#define NHEAD   16
#define HDIM    32

typedef __nv_bfloat16 bf16;

// ---------------- scratch ---------------------------------------------------
__device__ bf16  g_xw_h [L_TOK * DMODEL], g_xw_l [L_TOK * DMODEL];
__device__ float g_qkv  [L_TOK * QKVDIM];
__device__ bf16  g_aw_h [L_TOK * DMODEL], g_aw_l [L_TOK * DMODEL];
__device__ float g_pro  [L_TOK * DMODEL];
__device__ float g_x1   [L_TOK * DMODEL];
__device__ bf16  g_x1_h [L_TOK * DMODEL], g_x1_l [L_TOK * DMODEL];
__device__ bf16  g_h_h  [L_TOK * FFNDIM], g_h_l  [L_TOK * FFNDIM];
__device__ float g_h2   [L_TOK * DMODEL];
__device__ float g_mod  [2048];

// pre-transposed + bf16-split weights, layout [N][K]
__device__ bf16 g_wqkv_h[QKVDIM * DMODEL], g_wqkv_l[QKVDIM * DMODEL];
__device__ bf16 g_wproj_h[DMODEL * DMODEL], g_wproj_l[DMODEL * DMODEL];
__device__ bf16 g_wfc1_h [FFNDIM * DMODEL], g_wfc1_l [FFNDIM * DMODEL];
__device__ bf16 g_wfc2_h [DMODEL * FFNDIM], g_wfc2_l [DMODEL * FFNDIM];

// ---------------- helpers ---------------------------------------------------
__device__ __forceinline__ uint32_t smem_u32(const void* p) {
    uint32_t a;
    asm("{ .reg .u64 t; cvta.to.shared.u64 t, %1; cvt.u32.u64 %0, t; }" : "=r"(a) : "l"(p));
    return a;
}
// pack: a -> low 16 bits, b -> high 16 bits
__device__ __forceinline__ uint32_t packlh(float a, float b) {
    uint32_t r;
    asm("cvt.rn.bf16x2.f32 %0, %1, %2;" : "=r"(r) : "f"(b), "f"(a));
    return r;
}
__device__ __forceinline__ void cpa16(uint32_t dst, const void* src) {
    asm volatile("cp.async.cg.shared.global [%0], [%1], 16;" :: "r"(dst), "l"(src) : "memory");
}
__device__ __forceinline__ void cp_commit() {
    asm volatile("cp.async.commit_group;" ::: "memory");
}
template<int N>
__device__ __forceinline__ void cp_wait() {
    asm volatile("cp.async.wait_group %0;" :: "n"(N) : "memory");
}
__device__ __forceinline__ void ldm4(uint32_t* r, uint32_t addr) {
    asm volatile("ldmatrix.sync.aligned.m8n8.x4.shared.b16 {%0,%1,%2,%3}, [%4];"
                 : "=r"(r[0]), "=r"(r[1]), "=r"(r[2]), "=r"(r[3]) : "r"(addr));
}
__device__ __forceinline__ void mma16816(float* d, const uint32_t* a,
                                         uint32_t b0, uint32_t b1) {
    asm volatile(
        "mma.sync.aligned.m16n8k16.row.col.f32.bf16.bf16.f32 "
        "{%0,%1,%2,%3},{%4,%5,%6,%7},{%8,%9},{%0,%1,%2,%3};"
        : "+f"(d[0]), "+f"(d[1]), "+f"(d[2]), "+f"(d[3])
        : "r"(a[0]), "r"(a[1]), "r"(a[2]), "r"(a[3]), "r"(b0), "r"(b1));
}

// ---------------- weight transpose + bf16 split -----------------------------
__global__ void wconv_kernel(const float* __restrict__ w,
                             bf16* __restrict__ oh, bf16* __restrict__ ol,
                             int K, int N)
{
    __shared__ float t[32][33];
    int n0 = blockIdx.x * 32, k0 = blockIdx.y * 32;
    int tx = threadIdx.x, ty = threadIdx.y;   // (32, 8)
    for (int i = ty; i < 32; i += 8)
        t[i][tx] = w[(size_t)(k0 + i) * N + n0 + tx];
    __syncthreads();
    for (int i = ty; i < 32; i += 8) {
        float f = t[tx][i];
        bf16 h = __float2bfloat16(f);
        bf16 l = __float2bfloat16(f - __bfloat162float(h));
        size_t o = (size_t)(n0 + i) * K + k0 + tx;
        oh[o] = h; ol[o] = l;
    }
}

// ---------------- mma.sync split-bf16 GEMM -----------------------------------
#define GST 32768u
#define GOA_H 0u
#define GOA_L 8192u
#define GOB_H 16384u
#define GOB_L 24576u

template<bool GELU, bool OUTSPLIT>
__global__ __launch_bounds__(256)
void gemm_mma(const bf16* __restrict__ Ah, const bf16* __restrict__ Al,
              const bf16* __restrict__ Bh, const bf16* __restrict__ Bl,
              const float* __restrict__ bias,
              float* __restrict__ Cf, bf16* __restrict__ Ch, bf16* __restrict__ Cl,
              int M, int N, int K)
{
    extern __shared__ char smc[];
    uint32_t sb = smem_u32(smc);
    int tid = threadIdx.x, wid = tid >> 5, lane = tid & 31;
    int wm = wid & 1, wn = wid >> 1;
    int bm = blockIdx.y * 128, bn = blockIdx.x * 128;

    int id0 = tid * 2;
    int row = id0 >> 2, c0 = id0 & 3;
    uint32_t doff[2]; int soff[2];
    #pragma unroll
    for (int l = 0; l < 2; l++) {
        int c = c0 + l;
        doff[l] = (uint32_t)(row * 64 + ((c ^ (row & 3)) << 4));
        soff[l] = c * 8;
    }
    const bf16* pAh = Ah + (size_t)(bm + row) * K;
    const bf16* pAl = Al + (size_t)(bm + row) * K;
    const bf16* pBh = Bh + (size_t)(bn + row) * K;
    const bf16* pBl = Bl + (size_t)(bn + row) * K;

    float acc[4][4][4];
    #pragma unroll
    for (int i = 0; i < 4; i++)
        #pragma unroll
        for (int j = 0; j < 4; j++)
            #pragma unroll
            for (int q = 0; q < 4; q++) acc[i][j][q] = 0.0f;

    int NC = K >> 5;
    {
        uint32_t base = sb;
        #pragma unroll
        for (int l = 0; l < 2; l++) {
            cpa16(base + GOA_H + doff[l], pAh + soff[l]);
            cpa16(base + GOA_L + doff[l], pAl + soff[l]);
            cpa16(base + GOB_H + doff[l], pBh + soff[l]);
            cpa16(base + GOB_L + doff[l], pBl + soff[l]);
        }
        cp_commit();
    }

    int arow = wm * 64 + (lane & 15);
    int akh  = lane >> 4;
    int brow = wn * 32 + (lane & 7) + ((lane >> 4) & 1) * 8;
    int bkh  = (lane >> 3) & 1;

    for (int kc = 0; kc < NC; kc++) {
        if (kc + 1 < NC) {
            uint32_t base = sb + ((kc + 1) & 1) * GST;
            int kof = (kc + 1) * 32;
            #pragma unroll
            for (int l = 0; l < 2; l++) {
                cpa16(base + GOA_H + doff[l], pAh + kof + soff[l]);
                cpa16(base + GOA_L + doff[l], pAl + kof + soff[l]);
                cpa16(base + GOB_H + doff[l], pBh + kof + soff[l]);
                cpa16(base + GOB_L + doff[l], pBl + kof + soff[l]);
            }
            cp_commit();
            cp_wait<1>();
        } else {
            cp_wait<0>();
        }
        __syncthreads();

        uint32_t base = sb + (kc & 1) * GST;
        #pragma unroll
        for (int ks = 0; ks < 2; ks++) {
            uint32_t ah[4][4], al[4][4], bh[2][4], bl[2][4];
            #pragma unroll
            for (int ma = 0; ma < 4; ma++) {
                int r = arow + ma * 16;
                int c = ks * 2 + akh;
                uint32_t off = (uint32_t)(r * 64 + ((c ^ (r & 3)) << 4));
                ldm4(ah[ma], base + GOA_H + off);
                ldm4(al[ma], base + GOA_L + off);
            }
            #pragma unroll
            for (int p = 0; p < 2; p++) {
                int r = brow + p * 16;
                int c = ks * 2 + bkh;
                uint32_t off = (uint32_t)(r * 64 + ((c ^ (r & 3)) << 4));
                ldm4(bh[p], base + GOB_H + off);
                ldm4(bl[p], base + GOB_L + off);
            }
            #pragma unroll
            for (int ma = 0; ma < 4; ma++)
                #pragma unroll
                for (int na = 0; na < 4; na++) {
                    uint32_t bh0 = bh[na >> 1][(na & 1) * 2];
                    uint32_t bh1 = bh[na >> 1][(na & 1) * 2 + 1];
                    uint32_t bl0 = bl[na >> 1][(na & 1) * 2];
                    uint32_t bl1 = bl[na >> 1][(na & 1) * 2 + 1];
                    mma16816(acc[ma][na], ah[ma], bh0, bh1);
                    mma16816(acc[ma][na], ah[ma], bl0, bl1);
                    mma16816(acc[ma][na], al[ma], bh0, bh1);
                }
        }
        __syncthreads();
    }

    int l4 = lane >> 2, l2 = (lane & 3) * 2;
    #pragma unroll
    for (int ma = 0; ma < 4; ma++) {
        int grow = bm + wm * 64 + ma * 16 + l4;
        #pragma unroll
        for (int na = 0; na < 4; na++) {
            int gcol = bn + wn * 32 + na * 8 + l2;
            float b0 = __ldg(bias + gcol), b1 = __ldg(bias + gcol + 1);
            float v[4];
            v[0] = acc[ma][na][0] + b0;  v[1] = acc[ma][na][1] + b1;
            v[2] = acc[ma][na][2] + b0;  v[3] = acc[ma][na][3] + b1;
            if (GELU) {
                #pragma unroll
                for (int q = 0; q < 4; q++)
                    v[q] = 0.5f * v[q] * (1.0f + erff(v[q] * 0.70710678118654752f));
            }
            #pragma unroll
            for (int half = 0; half < 2; half++) {
                size_t o = (size_t)(grow + half * 8) * N + gcol;
                float va = v[half * 2], vb = v[half * 2 + 1];
                if (OUTSPLIT) {
                    uint32_t hi = packlh(va, vb);
                    float la = va - __uint_as_float(hi << 16);
                    float lb = vb - __uint_as_float(hi & 0xffff0000u);
                    *(uint32_t*)(Ch + o) = hi;
                    *(uint32_t*)(Cl + o) = packlh(la, lb);
                } else {
                    float2 st; st.x = va; st.y = vb;
                    *(float2*)(Cf + o) = st;
                }
            }
        }
    }
}

// ---------------- mod GEMV ---------------------------------------------------
__global__ void mod_kernel(const float* __restrict__ c,
                           const float* __restrict__ w1, const float* __restrict__ b1,
                           const float* __restrict__ w2, const float* __restrict__ b2,
                           float* __restrict__ gmod)
{
    __shared__ float sc[512];
    int tid = threadIdx.x;
    for (int i = tid; i < 512; i += 256) {
        float v = c[i];
        sc[i] = v / (1.0f + __expf(-v));
    }
    __syncthreads();
    int o = blockIdx.x * 256 + tid;
    const float* w; const float* b; int col;
    if (o < 1024) { w = w1; b = b1; col = o; }
    else          { w = w2; b = b2; col = o - 1024; }
    float acc = b[col];
    for (int k = 0; k < 512; k++)
        acc += sc[k] * w[k * 1024 + col];
    gmod[o] = acc;
}

// ---------------- shift + window partition -> bf16 hi/lo ---------------------
__global__ void partition_kernel(const float* __restrict__ x,
                                 bf16* __restrict__ xh, bf16* __restrict__ xl)
{
    int row = blockIdx.x;
    int tid = threadIdx.x;
    int win = row / WTOK, n = row % WTOK;
    int wb = win & 7, hb = (win >> 3) & 15, cb = win >> 7;
    int i = n / 72, rem = n % 72, j = rem / 12, k = rem % 12;
    int cs = cb * 2 + i, hs = hb * 6 + j, ws = wb * 12 + k;
    int c0 = (cs + 1) & 3;
    int h0 = hs + 3;  if (h0 >= 96) h0 -= 96;
    int w0 = ws + 6;  if (w0 >= 96) w0 -= 96;
    size_t src = (size_t)((c0 * 96 + h0) * 96 + w0) * DMODEL;
    float4 f = ((const float4*)(x + src))[tid];
    uint32_t h01 = packlh(f.x, f.y), h23 = packlh(f.z, f.w);
    float l0 = f.x - __uint_as_float(h01 << 16);
    float l1 = f.y - __uint_as_float(h01 & 0xffff0000u);
    float l2 = f.z - __uint_as_float(h23 << 16);
    float l3 = f.w - __uint_as_float(h23 & 0xffff0000u);
    size_t o = (size_t)row * DMODEL + tid * 4;
    *(uint2*)(xh + o) = make_uint2(h01, h23);
    *(uint2*)(xl + o) = make_uint2(packlh(l0, l1), packlh(l2, l3));
}

// ---------------- windowed attention on tensor pipe --------------------------
// block = (win, head), 288 threads = 9 warps; warp w owns query rows 16w..16w+15.
// Q,K: [144][32] bf16 hi/lo, XOR-swizzled. Vt: [32][144] bf16 hi/lo.
#define AT_QH 0u
#define AT_QL 9216u
#define AT_KH 18432u
#define AT_KL 27648u
#define AT_VH 36864u
#define AT_VL 46080u
#define AT_LBL 55296u
#define AT_TOTAL 55872u

__global__ __launch_bounds__(288)
void attn_mma(const float* __restrict__ qkv,
              bf16* __restrict__ awh, bf16* __restrict__ awl)
{
    extern __shared__ char sm[];
    uint32_t sb = smem_u32(sm);
    int tid = threadIdx.x, warp = tid >> 5, lane = tid & 31;
    int bid = blockIdx.x;
    int win = bid >> 4, head = bid & 15;
    int wb = win & 7, hb = (win >> 3) & 15, cb = win >> 7;
    int* lbls = (int*)(sm + AT_LBL);

    const float* base = qkv + (size_t)win * WTOK * QKVDIM + head * HDIM;

    // stage Q, K (swizzled row-major) and V^T; bf16 hi/lo split
    for (int idx = tid; idx < WTOK * HDIM; idx += 288) {
        int n = idx >> 5, d = idx & 31;
        float q = base[(size_t)n * QKVDIM + d];
        float k = base[(size_t)n * QKVDIM + 512 + d];
        float v = base[(size_t)n * QKVDIM + 1024 + d];
        bf16 qh = __float2bfloat16(q); bf16 ql = __float2bfloat16(q - __bfloat162float(qh));
        bf16 kh = __float2bfloat16(k); bf16 kl = __float2bfloat16(k - __bfloat162float(kh));
        bf16 vh = __float2bfloat16(v); bf16 vl = __float2bfloat16(v - __bfloat162float(vh));
        uint32_t ro = (uint32_t)(n * 64 + (((d >> 3) ^ (n & 3)) << 4) + (d & 7) * 2);
        *(bf16*)(sm + AT_QH + ro) = qh;
        *(bf16*)(sm + AT_QL + ro) = ql;
        *(bf16*)(sm + AT_KH + ro) = kh;
        *(bf16*)(sm + AT_KL + ro) = kl;
        uint32_t vo = (uint32_t)(d * 288 + n * 2);
        *(bf16*)(sm + AT_VH + vo) = vh;
        *(bf16*)(sm + AT_VL + vo) = vl;
    }
    for (int n = tid; n < WTOK; n += 288) {
        int i = n / 72, rem = n % 72, j = rem / 12, k = rem % 12;
        int cs = cb * 2 + i, hs = hb * 6 + j, ws = wb * 12 + k;
        int lc = cs < 2 ? 0 : (cs < 3 ? 1 : 2);
        int lh = hs < 90 ? 0 : (hs < 93 ? 1 : 2);
        int lw = ws < 84 ? 0 : (ws < 90 ? 1 : 2);
        lbls[n] = lc * 9 + lh * 3 + lw;
    }
    __syncthreads();

    int R = warp * 16;

    // Q fragments (2 k16-tiles over d)
    uint32_t qfh[2][4], qfl[2][4];
    #pragma unroll
    for (int t = 0; t < 2; t++) {
        int r = R + (lane & 15);
        int c = t * 2 + (lane >> 4);
        uint32_t off = (uint32_t)(r * 64 + ((c ^ (r & 3)) << 4));
        ldm4(qfh[t], sb + AT_QH + off);
        ldm4(qfl[t], sb + AT_QL + off);
    }

    // S = Q K^T : 18 n-tiles x 4 regs
    float acc[18][4];
    #pragma unroll
    for (int nt = 0; nt < 18; nt++)
        #pragma unroll
        for (int q = 0; q < 4; q++) acc[nt][q] = 0.0f;

    #pragma unroll
    for (int t = 0; t < 2; t++) {
        #pragma unroll
        for (int jt = 0; jt < 9; jt++) {
            int r = jt * 16 + (lane & 7) + ((lane >> 4) & 1) * 8;
            int c = t * 2 + ((lane >> 3) & 1);
            uint32_t off = (uint32_t)(r * 64 + ((c ^ (r & 3)) << 4));
            uint32_t kh[4], kl[4];
            ldm4(kh, sb + AT_KH + off);
            ldm4(kl, sb + AT_KL + off);
            mma16816(acc[2*jt],   qfh[t], kh[0], kh[1]);
            mma16816(acc[2*jt],   qfh[t], kl[0], kl[1]);
            mma16816(acc[2*jt],   qfl[t], kh[0], kh[1]);
            mma16816(acc[2*jt+1], qfh[t], kh[2], kh[3]);
            mma16816(acc[2*jt+1], qfh[t], kl[2], kl[3]);
            mma16816(acc[2*jt+1], qfl[t], kh[2], kh[3]);
        }
    }

    // mask + softmax on fragments (rows r0 = R+l/4, r1 = r0+8)
    const float scale = 0.17677669529663688f;
    int r0 = R + (lane >> 2), r1 = r0 + 8;
    int li0 = lbls[r0], li1 = lbls[r1];
    float m0 = -1e30f, m1 = -1e30f;
    #pragma unroll
    for (int nt = 0; nt < 18; nt++) {
        int j0 = nt * 8 + (lane & 3) * 2;
        int lj0 = lbls[j0], lj1 = lbls[j0 + 1];
        acc[nt][0] = acc[nt][0] * scale + (lj0 == li0 ? 0.0f : -100.0f);
        acc[nt][1] = acc[nt][1] * scale + (lj1 == li0 ? 0.0f : -100.0f);
        acc[nt][2] = acc[nt][2] * scale + (lj0 == li1 ? 0.0f : -100.0f);
        acc[nt][3] = acc[nt][3] * scale + (lj1 == li1 ? 0.0f : -100.0f);
        m0 = fmaxf(m0, fmaxf(acc[nt][0], acc[nt][1]));
        m1 = fmaxf(m1, fmaxf(acc[nt][2], acc[nt][3]));
    }
    #pragma unroll
    for (int o = 1; o <= 2; o <<= 1) {
        m0 = fmaxf(m0, __shfl_xor_sync(0xffffffffu, m0, o));
        m1 = fmaxf(m1, __shfl_xor_sync(0xffffffffu, m1, o));
    }
    float s0 = 0.0f, s1 = 0.0f;
    #pragma unroll
    for (int nt = 0; nt < 18; nt++) {
        acc[nt][0] = __expf(acc[nt][0] - m0);  s0 += acc[nt][0];
        acc[nt][1] = __expf(acc[nt][1] - m0);  s0 += acc[nt][1];
        acc[nt][2] = __expf(acc[nt][2] - m1);  s1 += acc[nt][2];
        acc[nt][3] = __expf(acc[nt][3] - m1);  s1 += acc[nt][3];
    }
    #pragma unroll
    for (int o = 1; o <= 2; o <<= 1) {
        s0 += __shfl_xor_sync(0xffffffffu, s0, o);
        s1 += __shfl_xor_sync(0xffffffffu, s1, o);
    }
    float i0 = 1.0f / s0, i1 = 1.0f / s1;
    #pragma unroll
    for (int nt = 0; nt < 18; nt++) {
        acc[nt][0] *= i0; acc[nt][1] *= i0;
        acc[nt][2] *= i1; acc[nt][3] *= i1;
    }

    // PV: P (split bf16 from fragments) @ V (split), N = 32 (4 tiles)
    float pv[4][4];
    #pragma unroll
    for (int na = 0; na < 4; na++)
        #pragma unroll
        for (int q = 0; q < 4; q++) pv[na][q] = 0.0f;

    #pragma unroll
    for (int jt = 0; jt < 9; jt++) {
        uint32_t pah[4], pal[4];
        #pragma unroll
        for (int half = 0; half < 2; half++) {       // sub-tile 2jt / 2jt+1
            const float* p = acc[2 * jt + half];
            // rows r0: p[0], p[1];  rows r1: p[2], p[3]
            uint32_t h0 = packlh(p[0], p[1]);
            uint32_t h1 = packlh(p[2], p[3]);
            float l00 = p[0] - __uint_as_float(h0 << 16);
            float l01 = p[1] - __uint_as_float(h0 & 0xffff0000u);
            float l10 = p[2] - __uint_as_float(h1 << 16);
            float l11 = p[3] - __uint_as_float(h1 & 0xffff0000u);
            pah[half * 2]     = h0;  pah[half * 2 + 1] = h1;
            pal[half * 2]     = packlh(l00, l01);
            pal[half * 2 + 1] = packlh(l10, l11);
        }
        // pah/pal currently [tile0_r0, tile0_r1, tile1_r0, tile1_r1]
        // a-fragment order must be [r0_klo, r1_klo, r0_khi, r1_khi]:
        // tile 2jt = k-cols 0..7 (lo), tile 2jt+1 = 8..15 (hi) -> already matches.
        #pragma unroll
        for (int dv = 0; dv < 2; dv++) {
            int r = dv * 16 + (lane & 7) + ((lane >> 4) & 1) * 8;
            int c = jt * 2 + ((lane >> 3) & 1);
            uint32_t off = (uint32_t)(r * 288 + c * 16);
            uint32_t vh[4], vl[4];
            ldm4(vh, sb + AT_VH + off);
            ldm4(vl, sb + AT_VL + off);
            mma16816(pv[dv*2],   pah, vh[0], vh[1]);
            mma16816(pv[dv*2],   pah, vl[0], vl[1]);
            mma16816(pv[dv*2],   pal, vh[0], vh[1]);
            mma16816(pv[dv*2+1], pah, vh[2], vh[3]);
            mma16816(pv[dv*2+1], pah, vl[2], vl[3]);
            mma16816(pv[dv*2+1], pal, vh[2], vh[3]);
        }
    }

    // write out (bf16 hi/lo split), rows r0 / r1, cols head*32 + na*8 + (l&3)*2
    #pragma unroll
    for (int na = 0; na < 4; na++) {
        int col = head * HDIM + na * 8 + (lane & 3) * 2;
        #pragma unroll
        for (int half = 0; half < 2; half++) {
            int grow = win * WTOK + (half ? r1 : r0);
            float va = pv[na][half * 2], vb = pv[na][half * 2 + 1];
            size_t o = (size_t)grow * DMODEL + col;
            uint32_t hi = packlh(va, vb);
            float la = va - __uint_as_float(hi << 16);
            float lb = vb - __uint_as_float(hi & 0xffff0000u);
            *(uint32_t*)(awh + o) = hi;
            *(uint32_t*)(awl + o) = packlh(la, lb);
        }
    }
}

// ---------------- AdaLN + residual -------------------------------------------
template<bool PERM, bool SPLITOUT>
__global__ __launch_bounds__(128)
void adaln_kernel(const float* __restrict__ base, const float* __restrict__ src,
                  const float* __restrict__ shift, const float* __restrict__ scl,
                  float* __restrict__ out, bf16* __restrict__ oh, bf16* __restrict__ ol)
{
    int t = blockIdx.x, tid = threadIdx.x;
    size_t srow;
    if (PERM) {
        int c0 = t / (96 * 96); int r = t % (96 * 96);
        int h0 = r / 96, w0 = r % 96;
        int cs = (c0 + 3) & 3;
        int hs = h0 - 3; if (hs < 0) hs += 96;
        int ws = w0 - 6; if (ws < 0) ws += 96;
        int cb = cs >> 1, i = cs & 1;
        int hb = hs / 6,  j = hs % 6;
        int wb = ws / 12, k = ws % 12;
        srow = (size_t)(((cb * 16 + hb) * 8 + wb) * WTOK + (i * 6 + j) * 12 + k);
    } else {
        srow = (size_t)t;
    }
    float4 v = ((const float4*)(src + srow * DMODEL))[tid];
    float s  = v.x + v.y + v.z + v.w;
    float sq = v.x * v.x + v.y * v.y + v.z * v.z + v.w * v.w;
    for (int o = 16; o; o >>= 1) {
        s  += __shfl_xor_sync(0xffffffffu, s,  o);
        sq += __shfl_xor_sync(0xffffffffu, sq, o);
    }
    __shared__ float rs[4], rq[4];
    int w = tid >> 5, ln = tid & 31;
    if (ln == 0) { rs[w] = s; rq[w] = sq; }
    __syncthreads();
    float S = rs[0] + rs[1] + rs[2] + rs[3];
    float Q = rq[0] + rq[1] + rq[2] + rq[3];
    float mean = S * (1.0f / 512.0f);
    float var  = Q * (1.0f / 512.0f) - mean * mean;
    float rstd = rsqrtf(var + 1e-5f);

    float4 sh = ((const float4*)shift)[tid];
    float4 sc = ((const float4*)scl)[tid];
    float4 bx = ((const float4*)(base + (size_t)t * DMODEL))[tid];
    float4 o;
    o.x = bx.x + (v.x - mean) * rstd * sc.x + sh.x;
    o.y = bx.y + (v.y - mean) * rstd * sc.y + sh.y;
    o.z = bx.z + (v.z - mean) * rstd * sc.z + sh.z;
    o.w = bx.w + (v.w - mean) * rstd * sc.w + sh.w;
    ((float4*)(out + (size_t)t * DMODEL))[tid] = o;
    if (SPLITOUT) {
        uint32_t h01 = packlh(o.x, o.y), h23 = packlh(o.z, o.w);
        float l0 = o.x - __uint_as_float(h01 << 16);
        float l1 = o.y - __uint_as_float(h01 & 0xffff0000u);
        float l2 = o.z - __uint_as_float(h23 << 16);
        float l3 = o.w - __uint_as_float(h23 & 0xffff0000u);
        size_t oo = (size_t)t * DMODEL + tid * 4;
        *(uint2*)(oh + oo) = make_uint2(h01, h23);
        *(uint2*)(ol + oo) = make_uint2(packlh(l0, l1), packlh(l2, l3));
    }
}

// ---------------------------------------------------------------------------
extern "C" void kernel_launch(void* const* d_in, const int* in_sizes, int n_in,
                              void* d_out, int out_size)
{
    (void)in_sizes; (void)n_in; (void)out_size;
    const float* x      = (const float*)d_in[0];
    const float* c      = (const float*)d_in[1];
    const float* w_qkv  = (const float*)d_in[2];
    const float* b_qkv  = (const float*)d_in[3];
    const float* w_proj = (const float*)d_in[4];
    const float* b_proj = (const float*)d_in[5];
    const float* w_fc1  = (const float*)d_in[6];
    const float* b_fc1  = (const float*)d_in[7];
    const float* w_fc2  = (const float*)d_in[8];
    const float* b_fc2  = (const float*)d_in[9];
    const float* w_mod1 = (const float*)d_in[10];
    const float* b_mod1 = (const float*)d_in[11];
    const float* w_mod2 = (const float*)d_in[12];
    const float* b_mod2 = (const float*)d_in[13];
    float* out = (float*)d_out;

    float *p_qkv, *p_pro, *p_x1, *p_h2, *p_mod;
    bf16 *p_xwh, *p_xwl, *p_awh, *p_awl, *p_x1h, *p_x1l, *p_hh, *p_hl;
    cudaGetSymbolAddress((void**)&p_qkv, g_qkv);
    cudaGetSymbolAddress((void**)&p_pro, g_pro);
    cudaGetSymbolAddress((void**)&p_x1,  g_x1);
    cudaGetSymbolAddress((void**)&p_h2,  g_h2);
    cudaGetSymbolAddress((void**)&p_mod, g_mod);
    cudaGetSymbolAddress((void**)&p_xwh, g_xw_h); cudaGetSymbolAddress((void**)&p_xwl, g_xw_l);
    cudaGetSymbolAddress((void**)&p_awh, g_aw_h); cudaGetSymbolAddress((void**)&p_awl, g_aw_l);
    cudaGetSymbolAddress((void**)&p_x1h, g_x1_h); cudaGetSymbolAddress((void**)&p_x1l, g_x1_l);
    cudaGetSymbolAddress((void**)&p_hh,  g_h_h);  cudaGetSymbolAddress((void**)&p_hl,  g_h_l);

    bf16 *qh, *ql, *ph, *pl, *f1h, *f1l, *f2h, *f2l;
    cudaGetSymbolAddress((void**)&qh,  g_wqkv_h);  cudaGetSymbolAddress((void**)&ql,  g_wqkv_l);
    cudaGetSymbolAddress((void**)&ph,  g_wproj_h); cudaGetSymbolAddress((void**)&pl,  g_wproj_l);
    cudaGetSymbolAddress((void**)&f1h, g_wfc1_h);  cudaGetSymbolAddress((void**)&f1l, g_wfc1_l);
    cudaGetSymbolAddress((void**)&f2h, g_wfc2_h);  cudaGetSymbolAddress((void**)&f2l, g_wfc2_l);

    const int SMEM = 65536;
    cudaFuncSetAttribute(gemm_mma<false,false>, cudaFuncAttributeMaxDynamicSharedMemorySize, SMEM);
    cudaFuncSetAttribute(gemm_mma<true,true>,   cudaFuncAttributeMaxDynamicSharedMemorySize, SMEM);
    cudaFuncSetAttribute(attn_mma, cudaFuncAttributeMaxDynamicSharedMemorySize, AT_TOTAL);

    dim3 wcb(32, 8);
    wconv_kernel<<<dim3(QKVDIM / 32, DMODEL / 32), wcb>>>(w_qkv,  qh,  ql,  DMODEL, QKVDIM);
    wconv_kernel<<<dim3(DMODEL / 32, DMODEL / 32), wcb>>>(w_proj, ph,  pl,  DMODEL, DMODEL);
    wconv_kernel<<<dim3(FFNDIM / 32, DMODEL / 32), wcb>>>(w_fc1,  f1h, f1l, DMODEL, FFNDIM);
    wconv_kernel<<<dim3(DMODEL / 32, FFNDIM / 32), wcb>>>(w_fc2,  f2h, f2l, FFNDIM, DMODEL);

    mod_kernel<<<8, 256>>>(c, w_mod1, b_mod1, w_mod2, b_mod2, p_mod);
    partition_kernel<<<L_TOK, 128>>>(x, p_xwh, p_xwl);

    gemm_mma<false,false><<<dim3(QKVDIM / 128, L_TOK / 128), 256, SMEM>>>(
        p_xwh, p_xwl, qh, ql, b_qkv, p_qkv, nullptr, nullptr, L_TOK, QKVDIM, DMODEL);
    attn_mma<<<NWIN * NHEAD, 288, AT_TOTAL>>>(p_qkv, p_awh, p_awl);
    gemm_mma<false,false><<<dim3(DMODEL / 128, L_TOK / 128), 256, SMEM>>>(
        p_awh, p_awl, ph, pl, b_proj, p_pro, nullptr, nullptr, L_TOK, DMODEL, DMODEL);
    adaln_kernel<true,true><<<L_TOK, 128>>>(x, p_pro, p_mod, p_mod + 512, p_x1, p_x1h, p_x1l);
    gemm_mma<true,true><<<dim3(FFNDIM / 128, L_TOK / 128), 256, SMEM>>>(
        p_x1h, p_x1l, f1h, f1l, b_fc1, nullptr, p_hh, p_hl, L_TOK, FFNDIM, DMODEL);
    gemm_mma<false,false><<<dim3(DMODEL / 128, L_TOK / 128), 256, SMEM>>>(
        p_hh, p_hl, f2h, f2l, b_fc2, p_h2, nullptr, nullptr, L_TOK, DMODEL, FFNDIM);
    adaln_kernel<false,false><<<L_TOK, 128>>>(p_x1, p_h2, p_mod + 1024, p_mod + 1536,
                                              out, nullptr, nullptr);
}

// round 7
// speedup vs baseline: 2.5171x; 1.1001x over previous
#include <cuda_runtime.h>
#include <cuda_bf16.h>
#include <math.h>
#include <stdint.h>

// ---------------------------------------------------------------------------
// Swin3D block. GEMMs + attention on mma.sync m16n8k16 bf16 split-precision
// (hi+lo, 3 MMAs, fp32 accum). QKV GEMM emits attention-ready swizzled tiles;
// attention stages via cp.async and uses ldmatrix.trans for V.
// ---------------------------------------------------------------------------

#define L_TOK   36864
#define DMODEL  512
#define QKVDIM  1536
#define FFNDIM  2048
#define NWIN    256
#define WTOK    144
#define NHEAD   16
#define HDIM    32

typedef __nv_bfloat16 bf16;

// ---------------- scratch ---------------------------------------------------
__device__ bf16  g_xw_h [L_TOK * DMODEL], g_xw_l [L_TOK * DMODEL];
// qkv in attention-tile layout: [part(q/k/v)][win*16+head][144][32], swizzled
__device__ bf16  g_qkv_h[L_TOK * QKVDIM];
__device__ bf16  g_qkv_l[L_TOK * QKVDIM];
__device__ bf16  g_aw_h [L_TOK * DMODEL], g_aw_l [L_TOK * DMODEL];
__device__ float g_pro  [L_TOK * DMODEL];
__device__ float g_x1   [L_TOK * DMODEL];
__device__ bf16  g_x1_h [L_TOK * DMODEL], g_x1_l [L_TOK * DMODEL];
__device__ bf16  g_h_h  [L_TOK * FFNDIM], g_h_l  [L_TOK * FFNDIM];
__device__ float g_h2   [L_TOK * DMODEL];
__device__ float g_mod  [2048];

// pre-transposed + bf16-split weights, layout [N][K]
__device__ bf16 g_wqkv_h[QKVDIM * DMODEL], g_wqkv_l[QKVDIM * DMODEL];
__device__ bf16 g_wproj_h[DMODEL * DMODEL], g_wproj_l[DMODEL * DMODEL];
__device__ bf16 g_wfc1_h [FFNDIM * DMODEL], g_wfc1_l [FFNDIM * DMODEL];
__device__ bf16 g_wfc2_h [DMODEL * FFNDIM], g_wfc2_l [DMODEL * FFNDIM];

#define TILE_BYTES 9216            // 144*32*2
#define TILE_ELEMS 4608

// ---------------- helpers ---------------------------------------------------
__device__ __forceinline__ uint32_t smem_u32(const void* p) {
    uint32_t a;
    asm("{ .reg .u64 t; cvta.to.shared.u64 t, %1; cvt.u32.u64 %0, t; }" : "=r"(a) : "l"(p));
    return a;
}
__device__ __forceinline__ uint32_t packlh(float a, float b) {
    uint32_t r;
    asm("cvt.rn.bf16x2.f32 %0, %1, %2;" : "=r"(r) : "f"(b), "f"(a));
    return r;
}
__device__ __forceinline__ void cpa16(uint32_t dst, const void* src) {
    asm volatile("cp.async.cg.shared.global [%0], [%1], 16;" :: "r"(dst), "l"(src) : "memory");
}
__device__ __forceinline__ void cp_commit() {
    asm volatile("cp.async.commit_group;" ::: "memory");
}
template<int N>
__device__ __forceinline__ void cp_wait() {
    asm volatile("cp.async.wait_group %0;" :: "n"(N) : "memory");
}
__device__ __forceinline__ void ldm4(uint32_t* r, uint32_t addr) {
    asm volatile("ldmatrix.sync.aligned.m8n8.x4.shared.b16 {%0,%1,%2,%3}, [%4];"
                 : "=r"(r[0]), "=r"(r[1]), "=r"(r[2]), "=r"(r[3]) : "r"(addr));
}
__device__ __forceinline__ void ldm4t(uint32_t* r, uint32_t addr) {
    asm volatile("ldmatrix.sync.aligned.m8n8.x4.trans.shared.b16 {%0,%1,%2,%3}, [%4];"
                 : "=r"(r[0]), "=r"(r[1]), "=r"(r[2]), "=r"(r[3]) : "r"(addr));
}
__device__ __forceinline__ void mma16816(float* d, const uint32_t* a,
                                         uint32_t b0, uint32_t b1) {
    asm volatile(
        "mma.sync.aligned.m16n8k16.row.col.f32.bf16.bf16.f32 "
        "{%0,%1,%2,%3},{%4,%5,%6,%7},{%8,%9},{%0,%1,%2,%3};"
        : "+f"(d[0]), "+f"(d[1]), "+f"(d[2]), "+f"(d[3])
        : "r"(a[0]), "r"(a[1]), "r"(a[2]), "r"(a[3]), "r"(b0), "r"(b1));
}
// swizzled byte offset within a [144][32] bf16 tile
__device__ __forceinline__ uint32_t tsw(int n, int d) {
    return (uint32_t)(n * 64 + (((d >> 3) ^ (n & 3)) << 4) + (d & 7) * 2);
}

// ---------------- weight transpose + bf16 split -----------------------------
__global__ void wconv_kernel(const float* __restrict__ w,
                             bf16* __restrict__ oh, bf16* __restrict__ ol,
                             int K, int N)
{
    __shared__ float t[32][33];
    int n0 = blockIdx.x * 32, k0 = blockIdx.y * 32;
    int tx = threadIdx.x, ty = threadIdx.y;
    for (int i = ty; i < 32; i += 8)
        t[i][tx] = w[(size_t)(k0 + i) * N + n0 + tx];
    __syncthreads();
    for (int i = ty; i < 32; i += 8) {
        float f = t[tx][i];
        bf16 h = __float2bfloat16(f);
        bf16 l = __float2bfloat16(f - __bfloat162float(h));
        size_t o = (size_t)(n0 + i) * K + k0 + tx;
        oh[o] = h; ol[o] = l;
    }
}

// ---------------- mma.sync split-bf16 GEMM -----------------------------------
// OUTMODE: 0 = fp32 Cf, 1 = bf16 hi/lo split (Ch,Cl), 2 = qkv attention tiles
#define GST 32768u
#define GOA_H 0u
#define GOA_L 8192u
#define GOB_H 16384u
#define GOB_L 24576u

template<bool GELU, int OUTMODE>
__global__ __launch_bounds__(256)
void gemm_mma(const bf16* __restrict__ Ah, const bf16* __restrict__ Al,
              const bf16* __restrict__ Bh, const bf16* __restrict__ Bl,
              const float* __restrict__ bias,
              float* __restrict__ Cf, bf16* __restrict__ Ch, bf16* __restrict__ Cl,
              int M, int N, int K)
{
    extern __shared__ char smc[];
    uint32_t sb = smem_u32(smc);
    int tid = threadIdx.x, wid = tid >> 5, lane = tid & 31;
    int wm = wid & 1, wn = wid >> 1;
    int bm = blockIdx.y * 128, bn = blockIdx.x * 128;

    int id0 = tid * 2;
    int row = id0 >> 2, c0 = id0 & 3;
    uint32_t doff[2]; int soff[2];
    #pragma unroll
    for (int l = 0; l < 2; l++) {
        int c = c0 + l;
        doff[l] = (uint32_t)(row * 64 + ((c ^ (row & 3)) << 4));
        soff[l] = c * 8;
    }
    const bf16* pAh = Ah + (size_t)(bm + row) * K;
    const bf16* pAl = Al + (size_t)(bm + row) * K;
    const bf16* pBh = Bh + (size_t)(bn + row) * K;
    const bf16* pBl = Bl + (size_t)(bn + row) * K;

    float acc[4][4][4];
    #pragma unroll
    for (int i = 0; i < 4; i++)
        #pragma unroll
        for (int j = 0; j < 4; j++)
            #pragma unroll
            for (int q = 0; q < 4; q++) acc[i][j][q] = 0.0f;

    int NC = K >> 5;
    {
        uint32_t base = sb;
        #pragma unroll
        for (int l = 0; l < 2; l++) {
            cpa16(base + GOA_H + doff[l], pAh + soff[l]);
            cpa16(base + GOA_L + doff[l], pAl + soff[l]);
            cpa16(base + GOB_H + doff[l], pBh + soff[l]);
            cpa16(base + GOB_L + doff[l], pBl + soff[l]);
        }
        cp_commit();
    }

    int arow = wm * 64 + (lane & 15);
    int akh  = lane >> 4;
    int brow = wn * 32 + (lane & 7) + ((lane >> 4) & 1) * 8;
    int bkh  = (lane >> 3) & 1;

    for (int kc = 0; kc < NC; kc++) {
        if (kc + 1 < NC) {
            uint32_t base = sb + ((kc + 1) & 1) * GST;
            int kof = (kc + 1) * 32;
            #pragma unroll
            for (int l = 0; l < 2; l++) {
                cpa16(base + GOA_H + doff[l], pAh + kof + soff[l]);
                cpa16(base + GOA_L + doff[l], pAl + kof + soff[l]);
                cpa16(base + GOB_H + doff[l], pBh + kof + soff[l]);
                cpa16(base + GOB_L + doff[l], pBl + kof + soff[l]);
            }
            cp_commit();
            cp_wait<1>();
        } else {
            cp_wait<0>();
        }
        __syncthreads();

        uint32_t base = sb + (kc & 1) * GST;
        #pragma unroll
        for (int ks = 0; ks < 2; ks++) {
            uint32_t ah[4][4], al[4][4], bh[2][4], bl[2][4];
            #pragma unroll
            for (int ma = 0; ma < 4; ma++) {
                int r = arow + ma * 16;
                int c = ks * 2 + akh;
                uint32_t off = (uint32_t)(r * 64 + ((c ^ (r & 3)) << 4));
                ldm4(ah[ma], base + GOA_H + off);
                ldm4(al[ma], base + GOA_L + off);
            }
            #pragma unroll
            for (int p = 0; p < 2; p++) {
                int r = brow + p * 16;
                int c = ks * 2 + bkh;
                uint32_t off = (uint32_t)(r * 64 + ((c ^ (r & 3)) << 4));
                ldm4(bh[p], base + GOB_H + off);
                ldm4(bl[p], base + GOB_L + off);
            }
            #pragma unroll
            for (int ma = 0; ma < 4; ma++)
                #pragma unroll
                for (int na = 0; na < 4; na++) {
                    uint32_t bh0 = bh[na >> 1][(na & 1) * 2];
                    uint32_t bh1 = bh[na >> 1][(na & 1) * 2 + 1];
                    uint32_t bl0 = bl[na >> 1][(na & 1) * 2];
                    uint32_t bl1 = bl[na >> 1][(na & 1) * 2 + 1];
                    mma16816(acc[ma][na], ah[ma], bh0, bh1);
                    mma16816(acc[ma][na], ah[ma], bl0, bl1);
                    mma16816(acc[ma][na], al[ma], bh0, bh1);
                }
        }
        __syncthreads();
    }

    int l4 = lane >> 2, l2 = (lane & 3) * 2;
    #pragma unroll
    for (int ma = 0; ma < 4; ma++) {
        int grow0 = bm + wm * 64 + ma * 16 + l4;
        #pragma unroll
        for (int na = 0; na < 4; na++) {
            int gcol = bn + wn * 32 + na * 8 + l2;
            float b0 = __ldg(bias + gcol), b1 = __ldg(bias + gcol + 1);
            float v[4];
            v[0] = acc[ma][na][0] + b0;  v[1] = acc[ma][na][1] + b1;
            v[2] = acc[ma][na][2] + b0;  v[3] = acc[ma][na][3] + b1;
            if (GELU) {
                #pragma unroll
                for (int q = 0; q < 4; q++)
                    v[q] = 0.5f * v[q] * (1.0f + erff(v[q] * 0.70710678118654752f));
            }
            #pragma unroll
            for (int half = 0; half < 2; half++) {
                int grow = grow0 + half * 8;
                float va = v[half * 2], vb = v[half * 2 + 1];
                if (OUTMODE == 2) {
                    // qkv tiles: part = gcol/512, head = (gcol%512)/32, d = gcol%32
                    int part = gcol >> 9, rem = gcol & 511;
                    int head = rem >> 5, d = rem & 31;
                    int win = grow / 144, n = grow - win * 144;
                    size_t tb = ((size_t)part * NWIN * NHEAD + win * NHEAD + head) * TILE_BYTES;
                    uint32_t off = tsw(n, d);
                    uint32_t hi = packlh(va, vb);
                    float la = va - __uint_as_float(hi << 16);
                    float lb = vb - __uint_as_float(hi & 0xffff0000u);
                    *(uint32_t*)((char*)Ch + tb + off) = hi;
                    *(uint32_t*)((char*)Cl + tb + off) = packlh(la, lb);
                } else if (OUTMODE == 1) {
                    size_t o = (size_t)grow * N + gcol;
                    uint32_t hi = packlh(va, vb);
                    float la = va - __uint_as_float(hi << 16);
                    float lb = vb - __uint_as_float(hi & 0xffff0000u);
                    *(uint32_t*)(Ch + o) = hi;
                    *(uint32_t*)(Cl + o) = packlh(la, lb);
                } else {
                    size_t o = (size_t)grow * N + gcol;
                    float2 st; st.x = va; st.y = vb;
                    *(float2*)(Cf + o) = st;
                }
            }
        }
    }
}

// ---------------- mod GEMV ---------------------------------------------------
__global__ void mod_kernel(const float* __restrict__ c,
                           const float* __restrict__ w1, const float* __restrict__ b1,
                           const float* __restrict__ w2, const float* __restrict__ b2,
                           float* __restrict__ gmod)
{
    __shared__ float sc[512];
    int tid = threadIdx.x;
    for (int i = tid; i < 512; i += 256) {
        float v = c[i];
        sc[i] = v / (1.0f + __expf(-v));
    }
    __syncthreads();
    int o = blockIdx.x * 256 + tid;
    const float* w; const float* b; int col;
    if (o < 1024) { w = w1; b = b1; col = o; }
    else          { w = w2; b = b2; col = o - 1024; }
    float acc = b[col];
    for (int k = 0; k < 512; k++)
        acc += sc[k] * w[k * 1024 + col];
    gmod[o] = acc;
}

// ---------------- shift + window partition -> bf16 hi/lo ---------------------
__global__ void partition_kernel(const float* __restrict__ x,
                                 bf16* __restrict__ xh, bf16* __restrict__ xl)
{
    int row = blockIdx.x;
    int tid = threadIdx.x;
    int win = row / WTOK, n = row % WTOK;
    int wb = win & 7, hb = (win >> 3) & 15, cb = win >> 7;
    int i = n / 72, rem = n % 72, j = rem / 12, k = rem % 12;
    int cs = cb * 2 + i, hs = hb * 6 + j, ws = wb * 12 + k;
    int c0 = (cs + 1) & 3;
    int h0 = hs + 3;  if (h0 >= 96) h0 -= 96;
    int w0 = ws + 6;  if (w0 >= 96) w0 -= 96;
    size_t src = (size_t)((c0 * 96 + h0) * 96 + w0) * DMODEL;
    float4 f = ((const float4*)(x + src))[tid];
    uint32_t h01 = packlh(f.x, f.y), h23 = packlh(f.z, f.w);
    float l0 = f.x - __uint_as_float(h01 << 16);
    float l1 = f.y - __uint_as_float(h01 & 0xffff0000u);
    float l2 = f.z - __uint_as_float(h23 << 16);
    float l3 = f.w - __uint_as_float(h23 & 0xffff0000u);
    size_t o = (size_t)row * DMODEL + tid * 4;
    *(uint2*)(xh + o) = make_uint2(h01, h23);
    *(uint2*)(xl + o) = make_uint2(packlh(l0, l1), packlh(l2, l3));
}

// ---------------- windowed attention on tensor pipe --------------------------
// block = (win, head), 288 threads; staging = pure cp.async (layout matches).
#define AT_QH 0u
#define AT_QL 9216u
#define AT_KH 18432u
#define AT_KL 27648u
#define AT_VH 36864u
#define AT_VL 46080u
#define AT_LBL 55296u
#define AT_TOTAL 55872u

__global__ __launch_bounds__(288)
void attn_mma(const bf16* __restrict__ qkvh, const bf16* __restrict__ qkvl,
              bf16* __restrict__ awh, bf16* __restrict__ awl)
{
    extern __shared__ char sm[];
    uint32_t sb = smem_u32(sm);
    int tid = threadIdx.x, warp = tid >> 5, lane = tid & 31;
    int bid = blockIdx.x;
    int win = bid >> 4, head = bid & 15;
    int wb = win & 7, hb = (win >> 3) & 15, cb = win >> 7;
    int* lbls = (int*)(sm + AT_LBL);

    // cp.async staging: 6 tiles x 576 16B-chunks = 3456 chunks, 12 per thread
    {
        size_t t0 = ((size_t)0 * NWIN * NHEAD + win * NHEAD + head) * TILE_BYTES;
        size_t t1 = t0 + (size_t)NWIN * NHEAD * TILE_BYTES;
        size_t t2 = t1 + (size_t)NWIN * NHEAD * TILE_BYTES;
        const char* ph = (const char*)qkvh;
        const char* pl = (const char*)qkvl;
        #pragma unroll
        for (int it = 0; it < 2; it++) {
            int ch = it * 288 + tid;              // 0..575
            uint32_t off = (uint32_t)(ch * 16);
            cpa16(sb + AT_QH + off, ph + t0 + off);
            cpa16(sb + AT_QL + off, pl + t0 + off);
            cpa16(sb + AT_KH + off, ph + t1 + off);
            cpa16(sb + AT_KL + off, pl + t1 + off);
            cpa16(sb + AT_VH + off, ph + t2 + off);
            cpa16(sb + AT_VL + off, pl + t2 + off);
        }
        cp_commit();
    }
    for (int n = tid; n < WTOK; n += 288) {
        int i = n / 72, rem = n % 72, j = rem / 12, k = rem % 12;
        int cs = cb * 2 + i, hs = hb * 6 + j, ws = wb * 12 + k;
        int lc = cs < 2 ? 0 : (cs < 3 ? 1 : 2);
        int lh = hs < 90 ? 0 : (hs < 93 ? 1 : 2);
        int lw = ws < 84 ? 0 : (ws < 90 ? 1 : 2);
        lbls[n] = lc * 9 + lh * 3 + lw;
    }
    cp_wait<0>();
    __syncthreads();

    int R = warp * 16;

    uint32_t qfh[2][4], qfl[2][4];
    #pragma unroll
    for (int t = 0; t < 2; t++) {
        int r = R + (lane & 15);
        int c = t * 2 + (lane >> 4);
        uint32_t off = (uint32_t)(r * 64 + ((c ^ (r & 3)) << 4));
        ldm4(qfh[t], sb + AT_QH + off);
        ldm4(qfl[t], sb + AT_QL + off);
    }

    float acc[18][4];
    #pragma unroll
    for (int nt = 0; nt < 18; nt++)
        #pragma unroll
        for (int q = 0; q < 4; q++) acc[nt][q] = 0.0f;

    #pragma unroll
    for (int t = 0; t < 2; t++) {
        #pragma unroll
        for (int jt = 0; jt < 9; jt++) {
            int r = jt * 16 + (lane & 7) + ((lane >> 4) & 1) * 8;
            int c = t * 2 + ((lane >> 3) & 1);
            uint32_t off = (uint32_t)(r * 64 + ((c ^ (r & 3)) << 4));
            uint32_t kh[4], kl[4];
            ldm4(kh, sb + AT_KH + off);
            ldm4(kl, sb + AT_KL + off);
            mma16816(acc[2*jt],   qfh[t], kh[0], kh[1]);
            mma16816(acc[2*jt],   qfh[t], kl[0], kl[1]);
            mma16816(acc[2*jt],   qfl[t], kh[0], kh[1]);
            mma16816(acc[2*jt+1], qfh[t], kh[2], kh[3]);
            mma16816(acc[2*jt+1], qfh[t], kl[2], kl[3]);
            mma16816(acc[2*jt+1], qfl[t], kh[2], kh[3]);
        }
    }

    const float scale = 0.17677669529663688f;
    int r0 = R + (lane >> 2), r1 = r0 + 8;
    int li0 = lbls[r0], li1 = lbls[r1];
    float m0 = -1e30f, m1 = -1e30f;
    #pragma unroll
    for (int nt = 0; nt < 18; nt++) {
        int j0 = nt * 8 + (lane & 3) * 2;
        int lj0 = lbls[j0], lj1 = lbls[j0 + 1];
        acc[nt][0] = acc[nt][0] * scale + (lj0 == li0 ? 0.0f : -100.0f);
        acc[nt][1] = acc[nt][1] * scale + (lj1 == li0 ? 0.0f : -100.0f);
        acc[nt][2] = acc[nt][2] * scale + (lj0 == li1 ? 0.0f : -100.0f);
        acc[nt][3] = acc[nt][3] * scale + (lj1 == li1 ? 0.0f : -100.0f);
        m0 = fmaxf(m0, fmaxf(acc[nt][0], acc[nt][1]));
        m1 = fmaxf(m1, fmaxf(acc[nt][2], acc[nt][3]));
    }
    #pragma unroll
    for (int o = 1; o <= 2; o <<= 1) {
        m0 = fmaxf(m0, __shfl_xor_sync(0xffffffffu, m0, o));
        m1 = fmaxf(m1, __shfl_xor_sync(0xffffffffu, m1, o));
    }
    float s0 = 0.0f, s1 = 0.0f;
    #pragma unroll
    for (int nt = 0; nt < 18; nt++) {
        acc[nt][0] = __expf(acc[nt][0] - m0);  s0 += acc[nt][0];
        acc[nt][1] = __expf(acc[nt][1] - m0);  s0 += acc[nt][1];
        acc[nt][2] = __expf(acc[nt][2] - m1);  s1 += acc[nt][2];
        acc[nt][3] = __expf(acc[nt][3] - m1);  s1 += acc[nt][3];
    }
    #pragma unroll
    for (int o = 1; o <= 2; o <<= 1) {
        s0 += __shfl_xor_sync(0xffffffffu, s0, o);
        s1 += __shfl_xor_sync(0xffffffffu, s1, o);
    }
    float i0 = 1.0f / s0, i1 = 1.0f / s1;
    #pragma unroll
    for (int nt = 0; nt < 18; nt++) {
        acc[nt][0] *= i0; acc[nt][1] *= i0;
        acc[nt][2] *= i1; acc[nt][3] *= i1;
    }

    // PV: P split from fragments, V row-major via ldmatrix.trans
    float pv[4][4];
    #pragma unroll
    for (int na = 0; na < 4; na++)
        #pragma unroll
        for (int q = 0; q < 4; q++) pv[na][q] = 0.0f;

    #pragma unroll
    for (int jt = 0; jt < 9; jt++) {
        uint32_t pah[4], pal[4];
        #pragma unroll
        for (int half = 0; half < 2; half++) {
            const float* p = acc[2 * jt + half];
            uint32_t h0 = packlh(p[0], p[1]);
            uint32_t h1 = packlh(p[2], p[3]);
            float l00 = p[0] - __uint_as_float(h0 << 16);
            float l01 = p[1] - __uint_as_float(h0 & 0xffff0000u);
            float l10 = p[2] - __uint_as_float(h1 << 16);
            float l11 = p[3] - __uint_as_float(h1 & 0xffff0000u);
            pah[half * 2]     = h0;  pah[half * 2 + 1] = h1;
            pal[half * 2]     = packlh(l00, l01);
            pal[half * 2 + 1] = packlh(l10, l11);
        }
        // trans-ldmatrix V: rows j = jt*16 + (lane&15); col-block = dt*2 + (lane>>4)
        #pragma unroll
        for (int dt = 0; dt < 2; dt++) {
            int r = jt * 16 + (lane & 15);
            int cblk = dt * 2 + (lane >> 4);         // 8-col block index
            uint32_t off = (uint32_t)(r * 64 + ((cblk ^ (r & 3)) << 4));
            uint32_t vh[4], vl[4];
            ldm4t(vh, sb + AT_VH + off);
            ldm4t(vl, sb + AT_VL + off);
            mma16816(pv[dt*2],   pah, vh[0], vh[1]);
            mma16816(pv[dt*2],   pah, vl[0], vl[1]);
            mma16816(pv[dt*2],   pal, vh[0], vh[1]);
            mma16816(pv[dt*2+1], pah, vh[2], vh[3]);
            mma16816(pv[dt*2+1], pah, vl[2], vl[3]);
            mma16816(pv[dt*2+1], pal, vh[2], vh[3]);
        }
    }

    #pragma unroll
    for (int na = 0; na < 4; na++) {
        int col = head * HDIM + na * 8 + (lane & 3) * 2;
        #pragma unroll
        for (int half = 0; half < 2; half++) {
            int grow = win * WTOK + (half ? r1 : r0);
            float va = pv[na][half * 2], vb = pv[na][half * 2 + 1];
            size_t o = (size_t)grow * DMODEL + col;
            uint32_t hi = packlh(va, vb);
            float la = va - __uint_as_float(hi << 16);
            float lb = vb - __uint_as_float(hi & 0xffff0000u);
            *(uint32_t*)(awh + o) = hi;
            *(uint32_t*)(awl + o) = packlh(la, lb);
        }
    }
}

// ---------------- AdaLN + residual -------------------------------------------
template<bool PERM, bool SPLITOUT>
__global__ __launch_bounds__(128)
void adaln_kernel(const float* __restrict__ base, const float* __restrict__ src,
                  const float* __restrict__ shift, const float* __restrict__ scl,
                  float* __restrict__ out, bf16* __restrict__ oh, bf16* __restrict__ ol)
{
    int t = blockIdx.x, tid = threadIdx.x;
    size_t srow;
    if (PERM) {
        int c0 = t / (96 * 96); int r = t % (96 * 96);
        int h0 = r / 96, w0 = r % 96;
        int cs = (c0 + 3) & 3;
        int hs = h0 - 3; if (hs < 0) hs += 96;
        int ws = w0 - 6; if (ws < 0) ws += 96;
        int cb = cs >> 1, i = cs & 1;
        int hb = hs / 6,  j = hs % 6;
        int wb = ws / 12, k = ws % 12;
        srow = (size_t)(((cb * 16 + hb) * 8 + wb) * WTOK + (i * 6 + j) * 12 + k);
    } else {
        srow = (size_t)t;
    }
    float4 v = ((const float4*)(src + srow * DMODEL))[tid];
    float s  = v.x + v.y + v.z + v.w;
    float sq = v.x * v.x + v.y * v.y + v.z * v.z + v.w * v.w;
    for (int o = 16; o; o >>= 1) {
        s  += __shfl_xor_sync(0xffffffffu, s,  o);
        sq += __shfl_xor_sync(0xffffffffu, sq, o);
    }
    __shared__ float rs[4], rq[4];
    int w = tid >> 5, ln = tid & 31;
    if (ln == 0) { rs[w] = s; rq[w] = sq; }
    __syncthreads();
    float S = rs[0] + rs[1] + rs[2] + rs[3];
    float Q = rq[0] + rq[1] + rq[2] + rq[3];
    float mean = S * (1.0f / 512.0f);
    float var  = Q * (1.0f / 512.0f) - mean * mean;
    float rstd = rsqrtf(var + 1e-5f);

    float4 sh = ((const float4*)shift)[tid];
    float4 sc = ((const float4*)scl)[tid];
    float4 bx = ((const float4*)(base + (size_t)t * DMODEL))[tid];
    float4 o;
    o.x = bx.x + (v.x - mean) * rstd * sc.x + sh.x;
    o.y = bx.y + (v.y - mean) * rstd * sc.y + sh.y;
    o.z = bx.z + (v.z - mean) * rstd * sc.z + sh.z;
    o.w = bx.w + (v.w - mean) * rstd * sc.w + sh.w;
    ((float4*)(out + (size_t)t * DMODEL))[tid] = o;
    if (SPLITOUT) {
        uint32_t h01 = packlh(o.x, o.y), h23 = packlh(o.z, o.w);
        float l0 = o.x - __uint_as_float(h01 << 16);
        float l1 = o.y - __uint_as_float(h01 & 0xffff0000u);
        float l2 = o.z - __uint_as_float(h23 << 16);
        float l3 = o.w - __uint_as_float(h23 & 0xffff0000u);
        size_t oo = (size_t)t * DMODEL + tid * 4;
        *(uint2*)(oh + oo) = make_uint2(h01, h23);
        *(uint2*)(ol + oo) = make_uint2(packlh(l0, l1), packlh(l2, l3));
    }
}

// ---------------------------------------------------------------------------
extern "C" void kernel_launch(void* const* d_in, const int* in_sizes, int n_in,
                              void* d_out, int out_size)
{
    (void)in_sizes; (void)n_in; (void)out_size;
    const float* x      = (const float*)d_in[0];
    const float* c      = (const float*)d_in[1];
    const float* w_qkv  = (const float*)d_in[2];
    const float* b_qkv  = (const float*)d_in[3];
    const float* w_proj = (const float*)d_in[4];
    const float* b_proj = (const float*)d_in[5];
    const float* w_fc1  = (const float*)d_in[6];
    const float* b_fc1  = (const float*)d_in[7];
    const float* w_fc2  = (const float*)d_in[8];
    const float* b_fc2  = (const float*)d_in[9];
    const float* w_mod1 = (const float*)d_in[10];
    const float* b_mod1 = (const float*)d_in[11];
    const float* w_mod2 = (const float*)d_in[12];
    const float* b_mod2 = (const float*)d_in[13];
    float* out = (float*)d_out;

    float *p_pro, *p_x1, *p_h2, *p_mod;
    bf16 *p_xwh, *p_xwl, *p_qh, *p_ql, *p_awh, *p_awl, *p_x1h, *p_x1l, *p_hh, *p_hl;
    cudaGetSymbolAddress((void**)&p_pro, g_pro);
    cudaGetSymbolAddress((void**)&p_x1,  g_x1);
    cudaGetSymbolAddress((void**)&p_h2,  g_h2);
    cudaGetSymbolAddress((void**)&p_mod, g_mod);
    cudaGetSymbolAddress((void**)&p_xwh, g_xw_h); cudaGetSymbolAddress((void**)&p_xwl, g_xw_l);
    cudaGetSymbolAddress((void**)&p_qh,  g_qkv_h); cudaGetSymbolAddress((void**)&p_ql,  g_qkv_l);
    cudaGetSymbolAddress((void**)&p_awh, g_aw_h); cudaGetSymbolAddress((void**)&p_awl, g_aw_l);
    cudaGetSymbolAddress((void**)&p_x1h, g_x1_h); cudaGetSymbolAddress((void**)&p_x1l, g_x1_l);
    cudaGetSymbolAddress((void**)&p_hh,  g_h_h);  cudaGetSymbolAddress((void**)&p_hl,  g_h_l);

    bf16 *qh, *ql, *ph, *pl, *f1h, *f1l, *f2h, *f2l;
    cudaGetSymbolAddress((void**)&qh,  g_wqkv_h);  cudaGetSymbolAddress((void**)&ql,  g_wqkv_l);
    cudaGetSymbolAddress((void**)&ph,  g_wproj_h); cudaGetSymbolAddress((void**)&pl,  g_wproj_l);
    cudaGetSymbolAddress((void**)&f1h, g_wfc1_h);  cudaGetSymbolAddress((void**)&f1l, g_wfc1_l);
    cudaGetSymbolAddress((void**)&f2h, g_wfc2_h);  cudaGetSymbolAddress((void**)&f2l, g_wfc2_l);

    const int SMEM = 65536;
    cudaFuncSetAttribute(gemm_mma<false,0>, cudaFuncAttributeMaxDynamicSharedMemorySize, SMEM);
    cudaFuncSetAttribute(gemm_mma<false,2>, cudaFuncAttributeMaxDynamicSharedMemorySize, SMEM);
    cudaFuncSetAttribute(gemm_mma<true,1>,  cudaFuncAttributeMaxDynamicSharedMemorySize, SMEM);
    cudaFuncSetAttribute(attn_mma, cudaFuncAttributeMaxDynamicSharedMemorySize, AT_TOTAL);

    dim3 wcb(32, 8);
    wconv_kernel<<<dim3(QKVDIM / 32, DMODEL / 32), wcb>>>(w_qkv,  qh,  ql,  DMODEL, QKVDIM);
    wconv_kernel<<<dim3(DMODEL / 32, DMODEL / 32), wcb>>>(w_proj, ph,  pl,  DMODEL, DMODEL);
    wconv_kernel<<<dim3(FFNDIM / 32, DMODEL / 32), wcb>>>(w_fc1,  f1h, f1l, DMODEL, FFNDIM);
    wconv_kernel<<<dim3(DMODEL / 32, FFNDIM / 32), wcb>>>(w_fc2,  f2h, f2l, FFNDIM, DMODEL);

    mod_kernel<<<8, 256>>>(c, w_mod1, b_mod1, w_mod2, b_mod2, p_mod);
    partition_kernel<<<L_TOK, 128>>>(x, p_xwh, p_xwl);

    gemm_mma<false,2><<<dim3(QKVDIM / 128, L_TOK / 128), 256, SMEM>>>(
        p_xwh, p_xwl, qh, ql, b_qkv, nullptr, p_qh, p_ql, L_TOK, QKVDIM, DMODEL);
    attn_mma<<<NWIN * NHEAD, 288, AT_TOTAL>>>(p_qh, p_ql, p_awh, p_awl);
    gemm_mma<false,0><<<dim3(DMODEL / 128, L_TOK / 128), 256, SMEM>>>(
        p_awh, p_awl, ph, pl, b_proj, p_pro, nullptr, nullptr, L_TOK, DMODEL, DMODEL);
    adaln_kernel<true,true><<<L_TOK, 128>>>(x, p_pro, p_mod, p_mod + 512, p_x1, p_x1h, p_x1l);
    gemm_mma<true,1><<<dim3(FFNDIM / 128, L_TOK / 128), 256, SMEM>>>(
        p_x1h, p_x1l, f1h, f1l, b_fc1, nullptr, p_hh, p_hl, L_TOK, FFNDIM, DMODEL);
    gemm_mma<false,0><<<dim3(DMODEL / 128, L_TOK / 128), 256, SMEM>>>(
        p_hh, p_hl, f2h, f2l, b_fc2, p_h2, nullptr, nullptr, L_TOK, DMODEL, FFNDIM);
    adaln_kernel<false,false><<<L_TOK, 128>>>(p_x1, p_h2, p_mod + 1024, p_mod + 1536,
                                              out, nullptr, nullptr);
}

// round 9
// speedup vs baseline: 4.4244x; 1.7578x over previous
#include <cuda_runtime.h>
#include <cuda_fp16.h>
#include <math.h>
#include <stdint.h>

// ---------------------------------------------------------------------------
// Swin3D block. GEMMs + attention on mma.sync m16n8k16 fp16 (fp32 accum).
// Error budget: measured 2.5e-6 at 17-bit products => ~8e-5 at fp16. Margin 12x.
// 4-stage cp.async ring in GEMM; attention stages via cp.async; V via ldm.trans.
// (Resubmit of R8 — infra failure, kernel never ran.)
// ---------------------------------------------------------------------------

#define L_TOK   36864
#define DMODEL  512
#define QKVDIM  1536
#define FFNDIM  2048
#define NWIN    256
#define WTOK    144
#define NHEAD   16
#define HDIM    32

typedef __half fp16;

// ---------------- scratch ---------------------------------------------------
__device__ fp16  g_xw  [L_TOK * DMODEL];
// qkv in attention-tile layout: [part(q/k/v)][win*16+head][144][32], swizzled
__device__ fp16  g_qkv [L_TOK * QKVDIM];
__device__ fp16  g_aw  [L_TOK * DMODEL];
__device__ float g_pro [L_TOK * DMODEL];
__device__ float g_x1  [L_TOK * DMODEL];
__device__ fp16  g_x1f [L_TOK * DMODEL];
__device__ fp16  g_h   [L_TOK * FFNDIM];
__device__ float g_h2  [L_TOK * DMODEL];
__device__ float g_mod [2048];

// pre-transposed fp16 weights, layout [N][K]
__device__ fp16 g_wqkv [QKVDIM * DMODEL];
__device__ fp16 g_wproj[DMODEL * DMODEL];
__device__ fp16 g_wfc1 [FFNDIM * DMODEL];
__device__ fp16 g_wfc2 [DMODEL * FFNDIM];

#define TILE_BYTES 9216            // 144*32*2

// ---------------- helpers ---------------------------------------------------
__device__ __forceinline__ uint32_t smem_u32(const void* p) {
    uint32_t a;
    asm("{ .reg .u64 t; cvta.to.shared.u64 t, %1; cvt.u32.u64 %0, t; }" : "=r"(a) : "l"(p));
    return a;
}
// pack two fp32 -> f16x2 (a -> low half, b -> high half)
__device__ __forceinline__ uint32_t packh(float a, float b) {
    uint32_t r;
    asm("cvt.rn.f16x2.f32 %0, %1, %2;" : "=r"(r) : "f"(b), "f"(a));
    return r;
}
__device__ __forceinline__ void cpa16(uint32_t dst, const void* src) {
    asm volatile("cp.async.cg.shared.global [%0], [%1], 16;" :: "r"(dst), "l"(src) : "memory");
}
__device__ __forceinline__ void cp_commit() {
    asm volatile("cp.async.commit_group;" ::: "memory");
}
template<int N>
__device__ __forceinline__ void cp_wait() {
    asm volatile("cp.async.wait_group %0;" :: "n"(N) : "memory");
}
__device__ __forceinline__ void ldm4(uint32_t* r, uint32_t addr) {
    asm volatile("ldmatrix.sync.aligned.m8n8.x4.shared.b16 {%0,%1,%2,%3}, [%4];"
                 : "=r"(r[0]), "=r"(r[1]), "=r"(r[2]), "=r"(r[3]) : "r"(addr));
}
__device__ __forceinline__ void ldm4t(uint32_t* r, uint32_t addr) {
    asm volatile("ldmatrix.sync.aligned.m8n8.x4.trans.shared.b16 {%0,%1,%2,%3}, [%4];"
                 : "=r"(r[0]), "=r"(r[1]), "=r"(r[2]), "=r"(r[3]) : "r"(addr));
}
__device__ __forceinline__ void mma16816(float* d, const uint32_t* a,
                                         uint32_t b0, uint32_t b1) {
    asm volatile(
        "mma.sync.aligned.m16n8k16.row.col.f32.f16.f16.f32 "
        "{%0,%1,%2,%3},{%4,%5,%6,%7},{%8,%9},{%0,%1,%2,%3};"
        : "+f"(d[0]), "+f"(d[1]), "+f"(d[2]), "+f"(d[3])
        : "r"(a[0]), "r"(a[1]), "r"(a[2]), "r"(a[3]), "r"(b0), "r"(b1));
}
// swizzled byte offset within a [144][32] fp16 tile (64B rows)
__device__ __forceinline__ uint32_t tsw(int n, int d) {
    return (uint32_t)(n * 64 + (((d >> 3) ^ (n & 3)) << 4) + (d & 7) * 2);
}

// ---------------- weight transpose + fp16 ------------------------------------
__global__ void wconv_kernel(const float* __restrict__ w,
                             fp16* __restrict__ oh, int K, int N)
{
    __shared__ float t[32][33];
    int n0 = blockIdx.x * 32, k0 = blockIdx.y * 32;
    int tx = threadIdx.x, ty = threadIdx.y;   // (32, 8)
    for (int i = ty; i < 32; i += 8)
        t[i][tx] = w[(size_t)(k0 + i) * N + n0 + tx];
    __syncthreads();
    for (int i = ty; i < 32; i += 8)
        oh[(size_t)(n0 + i) * K + k0 + tx] = __float2half(t[tx][i]);
}

// ---------------- mma.sync fp16 GEMM, 4-stage cp.async ring ------------------
// OUTMODE: 0 = fp32 Cf, 1 = fp16 Ch, 2 = qkv attention tiles (fp16, swizzled)
#define GST 16384u          // bytes per stage (A 8K + B 8K)
#define GOB 8192u

template<bool GELU, int OUTMODE>
__global__ __launch_bounds__(256)
void gemm_mma(const fp16* __restrict__ A, const fp16* __restrict__ B,
              const float* __restrict__ bias,
              float* __restrict__ Cf, fp16* __restrict__ Ch,
              int M, int N, int K)
{
    extern __shared__ char smc[];
    uint32_t sb = smem_u32(smc);
    int tid = threadIdx.x, wid = tid >> 5, lane = tid & 31;
    int wm = wid & 1, wn = wid >> 1;            // warp tile 64x32
    int bm = blockIdx.y * 128, bn = blockIdx.x * 128;

    // cp.async mapping: per operand 512 chunks of 16B; 2 per thread
    int id0 = tid * 2;
    int row = id0 >> 2, c0 = id0 & 3;           // c0 in {0,2}
    uint32_t doff[2]; int soff[2];
    #pragma unroll
    for (int l = 0; l < 2; l++) {
        int c = c0 + l;
        doff[l] = (uint32_t)(row * 64 + ((c ^ (row & 3)) << 4));
        soff[l] = c * 8;
    }
    const fp16* pA = A + (size_t)(bm + row) * K;
    const fp16* pB = B + (size_t)(bn + row) * K;

    float acc[4][4][4];
    #pragma unroll
    for (int i = 0; i < 4; i++)
        #pragma unroll
        for (int j = 0; j < 4; j++)
            #pragma unroll
            for (int q = 0; q < 4; q++) acc[i][j][q] = 0.0f;

    int NC = K >> 5;

    // prologue: stages 0..2
    #pragma unroll
    for (int s = 0; s < 3; s++) {
        if (s < NC) {
            uint32_t base = sb + s * GST;
            int kof = s * 32;
            #pragma unroll
            for (int l = 0; l < 2; l++) {
                cpa16(base + doff[l],       pA + kof + soff[l]);
                cpa16(base + GOB + doff[l], pB + kof + soff[l]);
            }
        }
        cp_commit();
    }

    int arow = wm * 64 + (lane & 15);
    int akh  = lane >> 4;
    int brow = wn * 32 + (lane & 7) + ((lane >> 4) & 1) * 8;
    int bkh  = (lane >> 3) & 1;

    for (int kc = 0; kc < NC; kc++) {
        cp_wait<2>();
        __syncthreads();

        uint32_t base = sb + (kc & 3) * GST;
        #pragma unroll
        for (int ks = 0; ks < 2; ks++) {
            uint32_t af[4][4], bfr[2][4];
            #pragma unroll
            for (int ma = 0; ma < 4; ma++) {
                int r = arow + ma * 16;
                int c = ks * 2 + akh;
                ldm4(af[ma], base + (uint32_t)(r * 64 + ((c ^ (r & 3)) << 4)));
            }
            #pragma unroll
            for (int p = 0; p < 2; p++) {
                int r = brow + p * 16;
                int c = ks * 2 + bkh;
                ldm4(bfr[p], base + GOB + (uint32_t)(r * 64 + ((c ^ (r & 3)) << 4)));
            }
            #pragma unroll
            for (int ma = 0; ma < 4; ma++)
                #pragma unroll
                for (int na = 0; na < 4; na++)
                    mma16816(acc[ma][na], af[ma],
                             bfr[na >> 1][(na & 1) * 2],
                             bfr[na >> 1][(na & 1) * 2 + 1]);
        }
        __syncthreads();

        int kn = kc + 3;
        if (kn < NC) {
            uint32_t nbase = sb + (kn & 3) * GST;
            int kof = kn * 32;
            #pragma unroll
            for (int l = 0; l < 2; l++) {
                cpa16(nbase + doff[l],       pA + kof + soff[l]);
                cpa16(nbase + GOB + doff[l], pB + kof + soff[l]);
            }
        }
        cp_commit();
    }

    // ---- epilogue
    int l4 = lane >> 2, l2 = (lane & 3) * 2;
    #pragma unroll
    for (int ma = 0; ma < 4; ma++) {
        int grow0 = bm + wm * 64 + ma * 16 + l4;
        #pragma unroll
        for (int na = 0; na < 4; na++) {
            int gcol = bn + wn * 32 + na * 8 + l2;
            float b0 = __ldg(bias + gcol), b1 = __ldg(bias + gcol + 1);
            float v[4];
            v[0] = acc[ma][na][0] + b0;  v[1] = acc[ma][na][1] + b1;
            v[2] = acc[ma][na][2] + b0;  v[3] = acc[ma][na][3] + b1;
            if (GELU) {
                #pragma unroll
                for (int q = 0; q < 4; q++)
                    v[q] = 0.5f * v[q] * (1.0f + erff(v[q] * 0.70710678118654752f));
            }
            #pragma unroll
            for (int half = 0; half < 2; half++) {
                int grow = grow0 + half * 8;
                float va = v[half * 2], vb = v[half * 2 + 1];
                if (OUTMODE == 2) {
                    int part = gcol >> 9, rem = gcol & 511;
                    int head = rem >> 5, d = rem & 31;
                    int win = grow / 144, n = grow - win * 144;
                    size_t tb = ((size_t)part * NWIN * NHEAD + win * NHEAD + head) * TILE_BYTES;
                    *(uint32_t*)((char*)Ch + tb + tsw(n, d)) = packh(va, vb);
                } else if (OUTMODE == 1) {
                    *(uint32_t*)(Ch + (size_t)grow * N + gcol) = packh(va, vb);
                } else {
                    float2 st; st.x = va; st.y = vb;
                    *(float2*)(Cf + (size_t)grow * N + gcol) = st;
                }
            }
        }
    }
}

// ---------------- mod GEMV ---------------------------------------------------
__global__ void mod_kernel(const float* __restrict__ c,
                           const float* __restrict__ w1, const float* __restrict__ b1,
                           const float* __restrict__ w2, const float* __restrict__ b2,
                           float* __restrict__ gmod)
{
    __shared__ float sc[512];
    int tid = threadIdx.x;
    for (int i = tid; i < 512; i += 256) {
        float v = c[i];
        sc[i] = v / (1.0f + __expf(-v));
    }
    __syncthreads();
    int o = blockIdx.x * 256 + tid;
    const float* w; const float* b; int col;
    if (o < 1024) { w = w1; b = b1; col = o; }
    else          { w = w2; b = b2; col = o - 1024; }
    float acc = b[col];
    for (int k = 0; k < 512; k++)
        acc += sc[k] * w[k * 1024 + col];
    gmod[o] = acc;
}

// ---------------- shift + window partition -> fp16 ---------------------------
__global__ void partition_kernel(const float* __restrict__ x, fp16* __restrict__ xw)
{
    int row = blockIdx.x;
    int tid = threadIdx.x;                     // 128 threads, float4 each
    int win = row / WTOK, n = row % WTOK;
    int wb = win & 7, hb = (win >> 3) & 15, cb = win >> 7;
    int i = n / 72, rem = n % 72, j = rem / 12, k = rem % 12;
    int cs = cb * 2 + i, hs = hb * 6 + j, ws = wb * 12 + k;
    int c0 = (cs + 1) & 3;
    int h0 = hs + 3;  if (h0 >= 96) h0 -= 96;
    int w0 = ws + 6;  if (w0 >= 96) w0 -= 96;
    size_t src = (size_t)((c0 * 96 + h0) * 96 + w0) * DMODEL;
    float4 f = ((const float4*)(x + src))[tid];
    size_t o = (size_t)row * DMODEL + tid * 4;
    *(uint2*)(xw + o) = make_uint2(packh(f.x, f.y), packh(f.z, f.w));
}

// ---------------- windowed attention on tensor pipe --------------------------
#define AT_Q   0u
#define AT_K   9216u
#define AT_V   18432u
#define AT_LBL 27648u
#define AT_TOTAL 28224u

__global__ __launch_bounds__(288)
void attn_mma(const fp16* __restrict__ qkv, fp16* __restrict__ aw)
{
    extern __shared__ char sm[];
    uint32_t sb = smem_u32(sm);
    int tid = threadIdx.x, warp = tid >> 5, lane = tid & 31;
    int bid = blockIdx.x;
    int win = bid >> 4, head = bid & 15;
    int wb = win & 7, hb = (win >> 3) & 15, cb = win >> 7;
    int* lbls = (int*)(sm + AT_LBL);

    // cp.async staging: 3 tiles x 576 chunks = 1728, 6 per thread
    {
        size_t t0 = ((size_t)win * NHEAD + head) * TILE_BYTES;
        size_t stp = (size_t)NWIN * NHEAD * TILE_BYTES;
        const char* p = (const char*)qkv;
        #pragma unroll
        for (int it = 0; it < 2; it++) {
            uint32_t off = (uint32_t)((it * 288 + tid) * 16);
            cpa16(sb + AT_Q + off, p + t0 + off);
            cpa16(sb + AT_K + off, p + t0 + stp + off);
            cpa16(sb + AT_V + off, p + t0 + 2 * stp + off);
        }
        cp_commit();
    }
    for (int n = tid; n < WTOK; n += 288) {
        int i = n / 72, rem = n % 72, j = rem / 12, k = rem % 12;
        int cs = cb * 2 + i, hs = hb * 6 + j, ws = wb * 12 + k;
        int lc = cs < 2 ? 0 : (cs < 3 ? 1 : 2);
        int lh = hs < 90 ? 0 : (hs < 93 ? 1 : 2);
        int lw = ws < 84 ? 0 : (ws < 90 ? 1 : 2);
        lbls[n] = lc * 9 + lh * 3 + lw;
    }
    cp_wait<0>();
    __syncthreads();

    int R = warp * 16;

    uint32_t qf[2][4];
    #pragma unroll
    for (int t = 0; t < 2; t++) {
        int r = R + (lane & 15);
        int c = t * 2 + (lane >> 4);
        ldm4(qf[t], sb + AT_Q + (uint32_t)(r * 64 + ((c ^ (r & 3)) << 4)));
    }

    float acc[18][4];
    #pragma unroll
    for (int nt = 0; nt < 18; nt++)
        #pragma unroll
        for (int q = 0; q < 4; q++) acc[nt][q] = 0.0f;

    #pragma unroll
    for (int t = 0; t < 2; t++) {
        #pragma unroll
        for (int jt = 0; jt < 9; jt++) {
            int r = jt * 16 + (lane & 7) + ((lane >> 4) & 1) * 8;
            int c = t * 2 + ((lane >> 3) & 1);
            uint32_t kf[4];
            ldm4(kf, sb + AT_K + (uint32_t)(r * 64 + ((c ^ (r & 3)) << 4)));
            mma16816(acc[2*jt],   qf[t], kf[0], kf[1]);
            mma16816(acc[2*jt+1], qf[t], kf[2], kf[3]);
        }
    }

    const float scale = 0.17677669529663688f;
    int r0 = R + (lane >> 2), r1 = r0 + 8;
    int li0 = lbls[r0], li1 = lbls[r1];
    float m0 = -1e30f, m1 = -1e30f;
    #pragma unroll
    for (int nt = 0; nt < 18; nt++) {
        int j0 = nt * 8 + (lane & 3) * 2;
        int lj0 = lbls[j0], lj1 = lbls[j0 + 1];
        acc[nt][0] = acc[nt][0] * scale + (lj0 == li0 ? 0.0f : -100.0f);
        acc[nt][1] = acc[nt][1] * scale + (lj1 == li0 ? 0.0f : -100.0f);
        acc[nt][2] = acc[nt][2] * scale + (lj0 == li1 ? 0.0f : -100.0f);
        acc[nt][3] = acc[nt][3] * scale + (lj1 == li1 ? 0.0f : -100.0f);
        m0 = fmaxf(m0, fmaxf(acc[nt][0], acc[nt][1]));
        m1 = fmaxf(m1, fmaxf(acc[nt][2], acc[nt][3]));
    }
    #pragma unroll
    for (int o = 1; o <= 2; o <<= 1) {
        m0 = fmaxf(m0, __shfl_xor_sync(0xffffffffu, m0, o));
        m1 = fmaxf(m1, __shfl_xor_sync(0xffffffffu, m1, o));
    }
    float s0 = 0.0f, s1 = 0.0f;
    #pragma unroll
    for (int nt = 0; nt < 18; nt++) {
        acc[nt][0] = __expf(acc[nt][0] - m0);  s0 += acc[nt][0];
        acc[nt][1] = __expf(acc[nt][1] - m0);  s0 += acc[nt][1];
        acc[nt][2] = __expf(acc[nt][2] - m1);  s1 += acc[nt][2];
        acc[nt][3] = __expf(acc[nt][3] - m1);  s1 += acc[nt][3];
    }
    #pragma unroll
    for (int o = 1; o <= 2; o <<= 1) {
        s0 += __shfl_xor_sync(0xffffffffu, s0, o);
        s1 += __shfl_xor_sync(0xffffffffu, s1, o);
    }
    float i0 = 1.0f / s0, i1 = 1.0f / s1;
    #pragma unroll
    for (int nt = 0; nt < 18; nt++) {
        acc[nt][0] *= i0; acc[nt][1] *= i0;
        acc[nt][2] *= i1; acc[nt][3] *= i1;
    }

    // PV: P packed fp16 from fragments, V row-major via ldmatrix.trans
    float pv[4][4];
    #pragma unroll
    for (int na = 0; na < 4; na++)
        #pragma unroll
        for (int q = 0; q < 4; q++) pv[na][q] = 0.0f;

    #pragma unroll
    for (int jt = 0; jt < 9; jt++) {
        uint32_t pa[4];
        pa[0] = packh(acc[2*jt][0],   acc[2*jt][1]);
        pa[1] = packh(acc[2*jt][2],   acc[2*jt][3]);
        pa[2] = packh(acc[2*jt+1][0], acc[2*jt+1][1]);
        pa[3] = packh(acc[2*jt+1][2], acc[2*jt+1][3]);
        #pragma unroll
        for (int dt = 0; dt < 2; dt++) {
            int r = jt * 16 + (lane & 15);
            int cblk = dt * 2 + (lane >> 4);
            uint32_t vf[4];
            ldm4t(vf, sb + AT_V + (uint32_t)(r * 64 + ((cblk ^ (r & 3)) << 4)));
            mma16816(pv[dt*2],   pa, vf[0], vf[1]);
            mma16816(pv[dt*2+1], pa, vf[2], vf[3]);
        }
    }

    #pragma unroll
    for (int na = 0; na < 4; na++) {
        int col = head * HDIM + na * 8 + (lane & 3) * 2;
        #pragma unroll
        for (int half = 0; half < 2; half++) {
            int grow = win * WTOK + (half ? r1 : r0);
            *(uint32_t*)(aw + (size_t)grow * DMODEL + col) =
                packh(pv[na][half * 2], pv[na][half * 2 + 1]);
        }
    }
}

// ---------------- AdaLN + residual -------------------------------------------
template<bool PERM, bool HOUT>
__global__ __launch_bounds__(128)
void adaln_kernel(const float* __restrict__ base, const float* __restrict__ src,
                  const float* __restrict__ shift, const float* __restrict__ scl,
                  float* __restrict__ out, fp16* __restrict__ oh)
{
    int t = blockIdx.x, tid = threadIdx.x;
    size_t srow;
    if (PERM) {
        int c0 = t / (96 * 96); int r = t % (96 * 96);
        int h0 = r / 96, w0 = r % 96;
        int cs = (c0 + 3) & 3;
        int hs = h0 - 3; if (hs < 0) hs += 96;
        int ws = w0 - 6; if (ws < 0) ws += 96;
        int cb = cs >> 1, i = cs & 1;
        int hb = hs / 6,  j = hs % 6;
        int wb = ws / 12, k = ws % 12;
        srow = (size_t)(((cb * 16 + hb) * 8 + wb) * WTOK + (i * 6 + j) * 12 + k);
    } else {
        srow = (size_t)t;
    }
    float4 v = ((const float4*)(src + srow * DMODEL))[tid];
    float s  = v.x + v.y + v.z + v.w;
    float sq = v.x * v.x + v.y * v.y + v.z * v.z + v.w * v.w;
    for (int o = 16; o; o >>= 1) {
        s  += __shfl_xor_sync(0xffffffffu, s,  o);
        sq += __shfl_xor_sync(0xffffffffu, sq, o);
    }
    __shared__ float rs[4], rq[4];
    int w = tid >> 5, ln = tid & 31;
    if (ln == 0) { rs[w] = s; rq[w] = sq; }
    __syncthreads();
    float S = rs[0] + rs[1] + rs[2] + rs[3];
    float Q = rq[0] + rq[1] + rq[2] + rq[3];
    float mean = S * (1.0f / 512.0f);
    float var  = Q * (1.0f / 512.0f) - mean * mean;
    float rstd = rsqrtf(var + 1e-5f);

    float4 sh = ((const float4*)shift)[tid];
    float4 sc = ((const float4*)scl)[tid];
    float4 bx = ((const float4*)(base + (size_t)t * DMODEL))[tid];
    float4 o;
    o.x = bx.x + (v.x - mean) * rstd * sc.x + sh.x;
    o.y = bx.y + (v.y - mean) * rstd * sc.y + sh.y;
    o.z = bx.z + (v.z - mean) * rstd * sc.z + sh.z;
    o.w = bx.w + (v.w - mean) * rstd * sc.w + sh.w;
    ((float4*)(out + (size_t)t * DMODEL))[tid] = o;
    if (HOUT) {
        size_t oo = (size_t)t * DMODEL + tid * 4;
        *(uint2*)(oh + oo) = make_uint2(packh(o.x, o.y), packh(o.z, o.w));
    }
}

// ---------------------------------------------------------------------------
extern "C" void kernel_launch(void* const* d_in, const int* in_sizes, int n_in,
                              void* d_out, int out_size)
{
    (void)in_sizes; (void)n_in; (void)out_size;
    const float* x      = (const float*)d_in[0];
    const float* c      = (const float*)d_in[1];
    const float* w_qkv  = (const float*)d_in[2];
    const float* b_qkv  = (const float*)d_in[3];
    const float* w_proj = (const float*)d_in[4];
    const float* b_proj = (const float*)d_in[5];
    const float* w_fc1  = (const float*)d_in[6];
    const float* b_fc1  = (const float*)d_in[7];
    const float* w_fc2  = (const float*)d_in[8];
    const float* b_fc2  = (const float*)d_in[9];
    const float* w_mod1 = (const float*)d_in[10];
    const float* b_mod1 = (const float*)d_in[11];
    const float* w_mod2 = (const float*)d_in[12];
    const float* b_mod2 = (const float*)d_in[13];
    float* out = (float*)d_out;

    float *p_pro, *p_x1, *p_h2, *p_mod;
    fp16 *p_xw, *p_q, *p_aw, *p_x1f, *p_h;
    cudaGetSymbolAddress((void**)&p_pro, g_pro);
    cudaGetSymbolAddress((void**)&p_x1,  g_x1);
    cudaGetSymbolAddress((void**)&p_h2,  g_h2);
    cudaGetSymbolAddress((void**)&p_mod, g_mod);
    cudaGetSymbolAddress((void**)&p_xw,  g_xw);
    cudaGetSymbolAddress((void**)&p_q,   g_qkv);
    cudaGetSymbolAddress((void**)&p_aw,  g_aw);
    cudaGetSymbolAddress((void**)&p_x1f, g_x1f);
    cudaGetSymbolAddress((void**)&p_h,   g_h);

    fp16 *qw, *pw, *f1w, *f2w;
    cudaGetSymbolAddress((void**)&qw,  g_wqkv);
    cudaGetSymbolAddress((void**)&pw,  g_wproj);
    cudaGetSymbolAddress((void**)&f1w, g_wfc1);
    cudaGetSymbolAddress((void**)&f2w, g_wfc2);

    const int SMEM = 65536;   // 4 stages x 16KB
    cudaFuncSetAttribute(gemm_mma<false,0>, cudaFuncAttributeMaxDynamicSharedMemorySize, SMEM);
    cudaFuncSetAttribute(gemm_mma<false,2>, cudaFuncAttributeMaxDynamicSharedMemorySize, SMEM);
    cudaFuncSetAttribute(gemm_mma<true,1>,  cudaFuncAttributeMaxDynamicSharedMemorySize, SMEM);
    cudaFuncSetAttribute(attn_mma, cudaFuncAttributeMaxDynamicSharedMemorySize, AT_TOTAL);

    dim3 wcb(32, 8);
    wconv_kernel<<<dim3(QKVDIM / 32, DMODEL / 32), wcb>>>(w_qkv,  qw,  DMODEL, QKVDIM);
    wconv_kernel<<<dim3(DMODEL / 32, DMODEL / 32), wcb>>>(w_proj, pw,  DMODEL, DMODEL);
    wconv_kernel<<<dim3(FFNDIM / 32, DMODEL / 32), wcb>>>(w_fc1,  f1w, DMODEL, FFNDIM);
    wconv_kernel<<<dim3(DMODEL / 32, FFNDIM / 32), wcb>>>(w_fc2,  f2w, FFNDIM, DMODEL);

    mod_kernel<<<8, 256>>>(c, w_mod1, b_mod1, w_mod2, b_mod2, p_mod);
    partition_kernel<<<L_TOK, 128>>>(x, p_xw);

    gemm_mma<false,2><<<dim3(QKVDIM / 128, L_TOK / 128), 256, SMEM>>>(
        p_xw, qw, b_qkv, nullptr, p_q, L_TOK, QKVDIM, DMODEL);
    attn_mma<<<NWIN * NHEAD, 288, AT_TOTAL>>>(p_q, p_aw);
    gemm_mma<false,0><<<dim3(DMODEL / 128, L_TOK / 128), 256, SMEM>>>(
        p_aw, pw, b_proj, p_pro, nullptr, L_TOK, DMODEL, DMODEL);
    adaln_kernel<true,true><<<L_TOK, 128>>>(x, p_pro, p_mod, p_mod + 512, p_x1, p_x1f);
    gemm_mma<true,1><<<dim3(FFNDIM / 128, L_TOK / 128), 256, SMEM>>>(
        p_x1f, f1w, b_fc1, nullptr, p_h, L_TOK, FFNDIM, DMODEL);
    gemm_mma<false,0><<<dim3(DMODEL / 128, L_TOK / 128), 256, SMEM>>>(
        p_h, f2w, b_fc2, p_h2, nullptr, L_TOK, DMODEL, FFNDIM);
    adaln_kernel<false,false><<<L_TOK, 128>>>(p_x1, p_h2, p_mod + 1024, p_mod + 1536,
                                              out, nullptr);
}